// round 9
// baseline (speedup 1.0000x reference)
#include <cuda_runtime.h>
#include <cuda_bf16.h>
#include <math.h>
#include <stdint.h>

// Problem constants
#define Bc      4
#define Lc      2048
#define Dc      1024
#define DIc     2048
#define TWO_DIc 4096
#define Nc      16
#define Kc      4
#define Rc      64
#define RNc     96    // R + 2N
#define CH      16    // scan chunks
#define CL      (Lc / CH)   // 128 timesteps per chunk

// fp32 scratch
__device__ float g_xz [(size_t)Bc * Lc * TWO_DIc];
__device__ float g_xc [(size_t)Bc * Lc * DIc];
__device__ float g_dbl[(size_t)Bc * Lc * RNc];
__device__ float g_dt [(size_t)Bc * Lc * DIc];

// chunked-scan intermediates: [b][d][chunk][n]
__device__ float g_S [(size_t)Bc * DIc * CH * Nc];
__device__ float g_P [(size_t)Bc * DIc * CH * Nc];
__device__ float g_H [(size_t)Bc * DIc * CH * Nc];

// bf16 split scratch (hi/lo)
__device__ __nv_bfloat16 g_xhi [(size_t)Bc * Lc * Dc];
__device__ __nv_bfloat16 g_xlo [(size_t)Bc * Lc * Dc];
__device__ __nv_bfloat16 g_wihi[(size_t)TWO_DIc * Dc];
__device__ __nv_bfloat16 g_wilo[(size_t)TWO_DIc * Dc];
__device__ __nv_bfloat16 g_yhi [(size_t)Bc * Lc * DIc];
__device__ __nv_bfloat16 g_ylo [(size_t)Bc * Lc * DIc];
__device__ __nv_bfloat16 g_wohi[(size_t)Dc * DIc];
__device__ __nv_bfloat16 g_wolo[(size_t)Dc * DIc];

// ---------------------------------------------------------------------------
// Helpers
// ---------------------------------------------------------------------------
__device__ __forceinline__ uint32_t smem_u32(const void* p) {
    uint32_t a;
    asm("{ .reg .u64 t; cvta.to.shared.u64 t, %1; cvt.u32.u64 %0, t; }"
        : "=r"(a) : "l"(p));
    return a;
}
__device__ __forceinline__ void cpa16(uint32_t dst, const void* src) {
    asm volatile("cp.async.cg.shared.global [%0], [%1], 16;"
                 :: "r"(dst), "l"(src) : "memory");
}
__device__ __forceinline__ void mma_bf16(float* c, const uint32_t* a, const uint32_t* b) {
    asm volatile(
        "mma.sync.aligned.m16n8k16.row.col.f32.bf16.bf16.f32 "
        "{%0,%1,%2,%3}, {%4,%5,%6,%7}, {%8,%9}, {%0,%1,%2,%3};"
        : "+f"(c[0]), "+f"(c[1]), "+f"(c[2]), "+f"(c[3])
        : "r"(a[0]), "r"(a[1]), "r"(a[2]), "r"(a[3]), "r"(b[0]), "r"(b[1]));
}
__device__ __forceinline__ void ldm_x4(uint32_t* r, uint32_t addr) {
    asm volatile("ldmatrix.sync.aligned.m8n8.x4.shared.b16 {%0,%1,%2,%3}, [%4];"
                 : "=r"(r[0]), "=r"(r[1]), "=r"(r[2]), "=r"(r[3]) : "r"(addr));
}
__device__ __forceinline__ void ldm_x2(uint32_t* r, uint32_t addr) {
    asm volatile("ldmatrix.sync.aligned.m8n8.x2.shared.b16 {%0,%1}, [%2];"
                 : "=r"(r[0]), "=r"(r[1]) : "r"(addr));
}

// ---------------------------------------------------------------------------
// Split fp32 -> bf16 hi/lo
// ---------------------------------------------------------------------------
__global__ void split_kernel(const float* __restrict__ src,
                             __nv_bfloat16* __restrict__ hi,
                             __nv_bfloat16* __restrict__ lo, int n)
{
    const int i = (blockIdx.x * blockDim.x + threadIdx.x) * 4;
    if (i >= n) return;
    const float4 v = *reinterpret_cast<const float4*>(src + i);
    __nv_bfloat16 h[4], l[4];
    const float f[4] = {v.x, v.y, v.z, v.w};
    #pragma unroll
    for (int j = 0; j < 4; ++j) {
        h[j] = __float2bfloat16(f[j]);
        l[j] = __float2bfloat16(f[j] - __bfloat162float(h[j]));
    }
    *reinterpret_cast<__nv_bfloat162*>(hi + i)     = __nv_bfloat162(h[0], h[1]);
    *reinterpret_cast<__nv_bfloat162*>(hi + i + 2) = __nv_bfloat162(h[2], h[3]);
    *reinterpret_cast<__nv_bfloat162*>(lo + i)     = __nv_bfloat162(l[0], l[1]);
    *reinterpret_cast<__nv_bfloat162*>(lo + i + 2) = __nv_bfloat162(l[2], l[3]);
}

// ---------------------------------------------------------------------------
// Split-bf16 tensor-core GEMM (HMMA), as in R7 (passing)
// ---------------------------------------------------------------------------
#define TSTAGE 40960
#define TROW   80

__global__ __launch_bounds__(256, 2)
void gemm_mma(const __nv_bfloat16* __restrict__ Ahi,
              const __nv_bfloat16* __restrict__ Alo,
              const __nv_bfloat16* __restrict__ Bhi,
              const __nv_bfloat16* __restrict__ Blo,
              float* __restrict__ C, int K, int ldc)
{
    extern __shared__ char smem[];
    const uint32_t sm0 = smem_u32(smem);
    const int tid  = threadIdx.x;
    const int wid  = tid >> 5;
    const int lane = tid & 31;
    const int wm   = wid >> 2;
    const int wn   = wid & 3;
    const int bm   = blockIdx.y * 128;
    const int bn   = blockIdx.x * 128;
    const int g    = lane >> 2;
    const int q    = lane & 3;

    const uint32_t aoffL = (uint32_t)(lane & 15) * TROW + (uint32_t)(lane >> 4) * 16;
    const uint32_t boffL = (uint32_t)(lane & 7) * TROW + (uint32_t)((lane >> 3) & 1) * 16;

    float acc[4][4][4] = {};

    auto stage_load = [&](int kt, int s) {
        const uint32_t sb = sm0 + s * TSTAGE;
        #pragma unroll
        for (int i = 0; i < 2; ++i) {
            const int idx = tid + 256 * i;
            const int row = idx >> 2;
            const int c4  = idx & 3;
            const uint32_t so = (uint32_t)row * TROW + c4 * 16;
            const size_t goA = (size_t)(bm + row) * K + kt + c4 * 8;
            const size_t goB = (size_t)(bn + row) * K + kt + c4 * 8;
            cpa16(sb + so,         Ahi + goA);
            cpa16(sb + 10240 + so, Alo + goA);
            cpa16(sb + 20480 + so, Bhi + goB);
            cpa16(sb + 30720 + so, Blo + goB);
        }
        asm volatile("cp.async.commit_group;" ::: "memory");
    };

    stage_load(0, 0);

    const int nt_iters = K / 32;
    for (int t = 0; t < nt_iters; ++t) {
        asm volatile("cp.async.wait_group 0;" ::: "memory");
        __syncthreads();
        if (t + 1 < nt_iters) stage_load((t + 1) * 32, (t + 1) & 1);

        const uint32_t stg = sm0 + (t & 1) * TSTAGE;
        #pragma unroll
        for (int ks = 0; ks < 2; ++ks) {
            uint32_t a_hi[4][4], a_lo[4][4];
            #pragma unroll
            for (int mt = 0; mt < 4; ++mt) {
                const uint32_t ab = stg + (uint32_t)(wm * 64 + mt * 16) * TROW
                                        + ks * 32 + aoffL;
                ldm_x4(a_hi[mt], ab);
                ldm_x4(a_lo[mt], ab + 10240);
            }
            #pragma unroll
            for (int nt = 0; nt < 4; ++nt) {
                const uint32_t bb = stg + 20480 + (uint32_t)(wn * 32 + nt * 8) * TROW
                                        + ks * 32 + boffL;
                uint32_t bh[2], bl2[2];
                ldm_x2(bh,  bb);
                ldm_x2(bl2, bb + 10240);
                #pragma unroll
                for (int mt = 0; mt < 4; ++mt) {
                    mma_bf16(acc[mt][nt], a_hi[mt], bh);
                    mma_bf16(acc[mt][nt], a_hi[mt], bl2);
                    mma_bf16(acc[mt][nt], a_lo[mt], bh);
                }
            }
        }
        __syncthreads();
    }

    #pragma unroll
    for (int mt = 0; mt < 4; ++mt) {
        const int r0 = bm + wm * 64 + mt * 16 + g;
        #pragma unroll
        for (int nt = 0; nt < 4; ++nt) {
            const int c0 = bn + wn * 32 + nt * 8 + q * 2;
            *reinterpret_cast<float2*>(&C[(size_t)r0 * ldc + c0]) =
                make_float2(acc[mt][nt][0], acc[mt][nt][1]);
            *reinterpret_cast<float2*>(&C[(size_t)(r0 + 8) * ldc + c0]) =
                make_float2(acc[mt][nt][2], acc[mt][nt][3]);
        }
    }
}

// ---------------------------------------------------------------------------
// Packed f32x2 helpers
// ---------------------------------------------------------------------------
__device__ __forceinline__ unsigned long long pk2(float lo, float hi) {
    unsigned long long r;
    asm("mov.b64 %0, {%1, %2};" : "=l"(r) : "f"(lo), "f"(hi));
    return r;
}
__device__ __forceinline__ void fma2(unsigned long long& d,
                                     unsigned long long a, unsigned long long b) {
    asm("fma.rn.f32x2 %0, %1, %2, %0;" : "+l"(d) : "l"(a), "l"(b));
}
__device__ __forceinline__ float2 upk2(unsigned long long v) {
    float2 f;
    asm("mov.b64 {%0, %1}, %2;" : "=f"(f.x), "=f"(f.y) : "l"(v));
    return f;
}

// ---------------------------------------------------------------------------
// Scalar NT SGEMM (f32x2, double-buffered) — GEMM2/GEMM3
// ---------------------------------------------------------------------------
template<int BM, int BN, int BK, int TM, int TN, int EPI>
__global__ __launch_bounds__((BM / TM) * (BN / TN), 2)
void gemm_nt(const float* __restrict__ A, int lda,
             const float* __restrict__ Bw, int ldb,
             float* __restrict__ C, int ldc,
             int M, int Nn, int K,
             const float* __restrict__ bias)
{
    constexpr int THREADS = (BM / TM) * (BN / TN);
    constexpr int VPR     = BK / 4;
    constexpr int RS      = THREADS / VPR;
    constexpr int AR      = BM / RS;
    constexpr int BR      = BN / RS;
    constexpr int LDA_S   = BM + 4;
    constexpr int LDB_S   = BN + 4;

    __shared__ float As[2][BK][LDA_S];
    __shared__ float Bs[2][BK][LDB_S];

    const int tid = threadIdx.x;
    const int tx  = tid % (BN / TN);
    const int ty  = tid / (BN / TN);
    const int bm  = blockIdx.y * BM;
    const int bn  = blockIdx.x * BN;
    const int lr  = tid / VPR;
    const int lc  = (tid % VPR) * 4;

    unsigned long long acc[TM][TN / 2] = {};
    float4 ar[AR], br[BR];

    auto ldg = [&](int kt) {
        #pragma unroll
        for (int i = 0; i < AR; ++i)
            ar[i] = *reinterpret_cast<const float4*>(
                &A[(size_t)(bm + i * RS + lr) * lda + kt + lc]);
        #pragma unroll
        for (int i = 0; i < BR; ++i) {
            const int n = bn + i * RS + lr;
            br[i] = (n < Nn)
                  ? *reinterpret_cast<const float4*>(&Bw[(size_t)n * ldb + kt + lc])
                  : make_float4(0.f, 0.f, 0.f, 0.f);
        }
    };
    auto sts = [&](int s) {
        #pragma unroll
        for (int i = 0; i < AR; ++i) {
            As[s][lc + 0][i * RS + lr] = ar[i].x;
            As[s][lc + 1][i * RS + lr] = ar[i].y;
            As[s][lc + 2][i * RS + lr] = ar[i].z;
            As[s][lc + 3][i * RS + lr] = ar[i].w;
        }
        #pragma unroll
        for (int i = 0; i < BR; ++i) {
            Bs[s][lc + 0][i * RS + lr] = br[i].x;
            Bs[s][lc + 1][i * RS + lr] = br[i].y;
            Bs[s][lc + 2][i * RS + lr] = br[i].z;
            Bs[s][lc + 3][i * RS + lr] = br[i].w;
        }
    };

    ldg(0);
    sts(0);
    __syncthreads();

    const int nt = K / BK;
    for (int t = 0; t < nt; ++t) {
        const int cur = t & 1;
        if (t + 1 < nt) ldg((t + 1) * BK);

        #pragma unroll
        for (int k = 0; k < BK; ++k) {
            float4 af[TM / 4], bf[TN / 4];
            #pragma unroll
            for (int i = 0; i < TM / 4; ++i)
                af[i] = *reinterpret_cast<const float4*>(&As[cur][k][ty * TM + 4 * i]);
            #pragma unroll
            for (int j = 0; j < TN / 4; ++j)
                bf[j] = *reinterpret_cast<const float4*>(&Bs[cur][k][tx * TN + 4 * j]);

            unsigned long long bp[TN / 2];
            #pragma unroll
            for (int j = 0; j < TN / 4; ++j) {
                bp[2 * j]     = pk2(bf[j].x, bf[j].y);
                bp[2 * j + 1] = pk2(bf[j].z, bf[j].w);
            }
            const float* afs = reinterpret_cast<const float*>(af);
            #pragma unroll
            for (int i = 0; i < TM; ++i) {
                const unsigned long long a2 = pk2(afs[i], afs[i]);
                #pragma unroll
                for (int j = 0; j < TN / 2; ++j)
                    fma2(acc[i][j], a2, bp[j]);
            }
        }

        if (t + 1 < nt) sts((t + 1) & 1);
        __syncthreads();
    }

    #pragma unroll
    for (int i = 0; i < TM; ++i) {
        const int row = bm + ty * TM + i;
        #pragma unroll
        for (int j = 0; j < TN / 2; ++j) {
            const int col = bn + tx * TN + 2 * j;
            if (col < Nn) {
                float2 p = upk2(acc[i][j]);
                if (EPI == 1) {
                    p.x += bias[col];
                    p.x = (p.x > 20.f) ? p.x : log1pf(__expf(p.x));
                    p.y += bias[col + 1];
                    p.y = (p.y > 20.f) ? p.y : log1pf(__expf(p.y));
                }
                *reinterpret_cast<float2*>(&C[(size_t)row * ldc + col]) = p;
            }
        }
    }
}

// ---------------------------------------------------------------------------
// Depthwise causal conv (K=4) + bias + silu
// ---------------------------------------------------------------------------
__global__ void conv_silu_kernel(const float* __restrict__ xz,
                                 const float* __restrict__ conv_w,
                                 const float* __restrict__ conv_b,
                                 float* __restrict__ xc)
{
    const int d = blockIdx.x * blockDim.x + threadIdx.x;
    const int l = blockIdx.y;
    const int b = blockIdx.z;

    float accv = conv_b[d];
    #pragma unroll
    for (int k = 0; k < Kc; ++k) {
        const int ls = l - (Kc - 1) + k;
        if (ls >= 0)
            accv = fmaf(xz[((size_t)b * Lc + ls) * TWO_DIc + d],
                        conv_w[d * Kc + k], accv);
    }
    const float s = accv / (1.f + __expf(-accv));
    xc[((size_t)b * Lc + l) * DIc + d] = s;
}

// ---------------------------------------------------------------------------
// Chunk-parallel selective scan.
// Phase 1: per (b,d,chunk) group of 16 lanes: local scan from h=0 over CL
//          steps; store end state S and decay product P per state n.
// ---------------------------------------------------------------------------
__global__ void scan_p1(const float* __restrict__ dt,
                        const float* __restrict__ dbl,
                        const float* __restrict__ xc,
                        const float* __restrict__ A_log,
                        float* __restrict__ S, float* __restrict__ P)
{
    const int gid  = blockIdx.x * (blockDim.x >> 4) + (threadIdx.x >> 4);
    const int lane = threadIdx.x & 15;
    const int c = gid & (CH - 1);
    const int d = (gid >> 4) & (DIc - 1);
    const int b = gid >> 15;

    const float An = -__expf(A_log[d * Nc + lane]);
    float h = 0.f, p = 1.f;

    const size_t base = (size_t)b * Lc + (size_t)c * CL;
    const float* dt_p = dt  + base * DIc + d;
    const float* xc_p = xc  + base * DIc + d;
    const float* bb_p = dbl + base * RNc + Rc + lane;

    for (int l = 0; l < CL; ++l) {
        const float dtv = dt_p[(size_t)l * DIc];
        const float xcv = xc_p[(size_t)l * DIc];
        const float Bn  = bb_p[(size_t)l * RNc];
        const float dA  = __expf(dtv * An);
        h = fmaf(dA, h, dtv * Bn * xcv);
        p *= dA;
    }
    const size_t o = (((size_t)b * DIc + d) * CH + c) * Nc + lane;
    S[o] = h;
    P[o] = p;
}

// Phase 2: per (b,d) group: sequential combine over CH chunks; store each
//          chunk's true start state Hst.
__global__ void scan_p2(const float* __restrict__ S,
                        const float* __restrict__ P,
                        float* __restrict__ Hst)
{
    const int gid  = blockIdx.x * (blockDim.x >> 4) + (threadIdx.x >> 4);
    const int lane = threadIdx.x & 15;
    const size_t base = (size_t)gid * CH * Nc + lane;

    float H = 0.f;
    #pragma unroll
    for (int c = 0; c < CH; ++c) {
        Hst[base + c * Nc] = H;
        H = fmaf(P[base + c * Nc], H, S[base + c * Nc]);
    }
}

// Phase 3: per (b,d,chunk) group: re-scan from true start state; emit y (bf16 hi/lo)
__global__ void scan_p3(const float* __restrict__ dt,
                        const float* __restrict__ dbl,
                        const float* __restrict__ xc,
                        const float* __restrict__ xz,
                        const float* __restrict__ A_log,
                        const float* __restrict__ D_param,
                        const float* __restrict__ Hst,
                        __nv_bfloat16* __restrict__ yhi,
                        __nv_bfloat16* __restrict__ ylo)
{
    const int gid  = blockIdx.x * (blockDim.x >> 4) + (threadIdx.x >> 4);
    const int lane = threadIdx.x & 15;
    const int c = gid & (CH - 1);
    const int d = (gid >> 4) & (DIc - 1);
    const int b = gid >> 15;

    const float An = -__expf(A_log[d * Nc + lane]);
    const float Dd = D_param[d];
    float h = Hst[(((size_t)b * DIc + d) * CH + c) * Nc + lane];

    const size_t base = (size_t)b * Lc + (size_t)c * CL;
    const float* dt_p = dt  + base * DIc + d;
    const float* xc_p = xc  + base * DIc + d;
    const float* z_p  = xz  + base * TWO_DIc + DIc + d;
    const float* bc_p = dbl + base * RNc + Rc;
    __nv_bfloat16* yh_p = yhi + base * DIc + d;
    __nv_bfloat16* yl_p = ylo + base * DIc + d;

    for (int l = 0; l < CL; ++l) {
        const float dtv = dt_p[(size_t)l * DIc];
        const float xcv = xc_p[(size_t)l * DIc];
        const float Bn  = bc_p[(size_t)l * RNc + lane];
        const float Cn  = bc_p[(size_t)l * RNc + Nc + lane];

        const float dA = __expf(dtv * An);
        h = fmaf(dA, h, dtv * Bn * xcv);

        float v = h * Cn;
        v += __shfl_xor_sync(0xffffffffu, v, 8);
        v += __shfl_xor_sync(0xffffffffu, v, 4);
        v += __shfl_xor_sync(0xffffffffu, v, 2);
        v += __shfl_xor_sync(0xffffffffu, v, 1);

        if (lane == 0) {
            const float zv = z_p[(size_t)l * TWO_DIc];
            float yv = (v + xcv * Dd) * (zv / (1.f + __expf(-zv)));
            const __nv_bfloat16 hh = __float2bfloat16(yv);
            yh_p[(size_t)l * DIc] = hh;
            yl_p[(size_t)l * DIc] = __float2bfloat16(yv - __bfloat162float(hh));
        }
    }
}

// ---------------------------------------------------------------------------
extern "C" void kernel_launch(void* const* d_in, const int* in_sizes, int n_in,
                              void* d_out, int out_size)
{
    const float* x       = (const float*)d_in[0];
    const float* W_in    = (const float*)d_in[1];
    const float* conv_w  = (const float*)d_in[2];
    const float* conv_b  = (const float*)d_in[3];
    const float* W_xproj = (const float*)d_in[4];
    const float* W_dt    = (const float*)d_in[5];
    const float* dt_bias = (const float*)d_in[6];
    const float* A_log   = (const float*)d_in[7];
    const float* D_param = (const float*)d_in[8];
    const float* W_out   = (const float*)d_in[9];
    float* out = (float*)d_out;

    float *xz, *xc, *dbl, *dtb, *Sb, *Pb, *Hb;
    __nv_bfloat16 *xhi, *xlo, *wihi, *wilo, *yhi, *ylo, *wohi, *wolo;
    cudaGetSymbolAddress((void**)&xz,   g_xz);
    cudaGetSymbolAddress((void**)&xc,   g_xc);
    cudaGetSymbolAddress((void**)&dbl,  g_dbl);
    cudaGetSymbolAddress((void**)&dtb,  g_dt);
    cudaGetSymbolAddress((void**)&Sb,   g_S);
    cudaGetSymbolAddress((void**)&Pb,   g_P);
    cudaGetSymbolAddress((void**)&Hb,   g_H);
    cudaGetSymbolAddress((void**)&xhi,  g_xhi);
    cudaGetSymbolAddress((void**)&xlo,  g_xlo);
    cudaGetSymbolAddress((void**)&wihi, g_wihi);
    cudaGetSymbolAddress((void**)&wilo, g_wilo);
    cudaGetSymbolAddress((void**)&yhi,  g_yhi);
    cudaGetSymbolAddress((void**)&ylo,  g_ylo);
    cudaGetSymbolAddress((void**)&wohi, g_wohi);
    cudaGetSymbolAddress((void**)&wolo, g_wolo);

    const int M = Bc * Lc;  // 8192
    const int TENSOR_SMEM = 2 * TSTAGE;

    cudaFuncSetAttribute(gemm_mma,
                         cudaFuncAttributeMaxDynamicSharedMemorySize, TENSOR_SMEM);

    // Split inputs to bf16 hi/lo
    split_kernel<<<(M * Dc / 4 + 255) / 256, 256>>>(x, xhi, xlo, M * Dc);
    split_kernel<<<(TWO_DIc * Dc / 4 + 255) / 256, 256>>>(W_in, wihi, wilo, TWO_DIc * Dc);
    split_kernel<<<(Dc * DIc / 4 + 255) / 256, 256>>>(W_out, wohi, wolo, Dc * DIc);

    // GEMM1 (tensor): xz[M,4096] = x @ W_in^T
    gemm_mma<<<dim3(TWO_DIc / 128, M / 128), 256, TENSOR_SMEM>>>(
        xhi, xlo, wihi, wilo, xz, Dc, TWO_DIc);

    // Depthwise causal conv + silu -> xc
    conv_silu_kernel<<<dim3(DIc / 256, Lc, Bc), 256>>>(xz, conv_w, conv_b, xc);

    // GEMM2 (scalar): dbl[M,96] = xc @ W_xproj^T
    gemm_nt<32, 128, 16, 4, 8, 0><<<dim3(1, M / 32), 128>>>(
        xc, DIc, W_xproj, DIc, dbl, RNc, M, RNc, DIc, nullptr);

    // GEMM3 (scalar): dt[M,2048] = softplus(dbl[:, :64] @ W_dt^T + dt_bias)
    gemm_nt<128, 128, 16, 8, 8, 1><<<dim3(DIc / 128, M / 128), 256>>>(
        dbl, RNc, W_dt, Rc, dtb, DIc, M, DIc, Rc, dt_bias);

    // Chunk-parallel scan
    scan_p1<<<(Bc * DIc * CH) / 16, 256>>>(dtb, dbl, xc, A_log, Sb, Pb);
    scan_p2<<<(Bc * DIc) / 16, 256>>>(Sb, Pb, Hb);
    scan_p3<<<(Bc * DIc * CH) / 16, 256>>>(dtb, dbl, xc, xz, A_log, D_param,
                                           Hb, yhi, ylo);

    // GEMM4 (tensor): out[M,1024] = y @ W_out^T
    gemm_mma<<<dim3(Dc / 128, M / 128), 256, TENSOR_SMEM>>>(
        yhi, ylo, wohi, wolo, out, DIc, Dc);
}

// round 11
// speedup vs baseline: 1.0231x; 1.0231x over previous
#include <cuda_runtime.h>
#include <cuda_bf16.h>
#include <math.h>
#include <stdint.h>

// Problem constants
#define Bc      4
#define Lc      2048
#define Dc      1024
#define DIc     2048
#define TWO_DIc 4096
#define Nc      16
#define Kc      4
#define Rc      64
#define RNc     96    // R + 2N
#define CH      16    // scan chunks
#define CL      (Lc / CH)   // 128 timesteps per chunk

// fp32 scratch
__device__ float g_xz [(size_t)Bc * Lc * TWO_DIc];
__device__ float g_xc [(size_t)Bc * Lc * DIc];
__device__ float g_dbl[(size_t)Bc * Lc * RNc];
__device__ float g_dt [(size_t)Bc * Lc * DIc];

// chunked-scan intermediates: [b][d][chunk][n]
__device__ float g_S [(size_t)Bc * DIc * CH * Nc];
__device__ float g_P [(size_t)Bc * DIc * CH * Nc];
__device__ float g_H [(size_t)Bc * DIc * CH * Nc];

// bf16 split scratch (hi/lo)
__device__ __nv_bfloat16 g_xhi [(size_t)Bc * Lc * Dc];
__device__ __nv_bfloat16 g_xlo [(size_t)Bc * Lc * Dc];
__device__ __nv_bfloat16 g_wihi[(size_t)TWO_DIc * Dc];
__device__ __nv_bfloat16 g_wilo[(size_t)TWO_DIc * Dc];
__device__ __nv_bfloat16 g_yhi [(size_t)Bc * Lc * DIc];
__device__ __nv_bfloat16 g_ylo [(size_t)Bc * Lc * DIc];
__device__ __nv_bfloat16 g_wohi[(size_t)Dc * DIc];
__device__ __nv_bfloat16 g_wolo[(size_t)Dc * DIc];

// ---------------------------------------------------------------------------
// Helpers
// ---------------------------------------------------------------------------
__device__ __forceinline__ uint32_t smem_u32(const void* p) {
    uint32_t a;
    asm("{ .reg .u64 t; cvta.to.shared.u64 t, %1; cvt.u32.u64 %0, t; }"
        : "=r"(a) : "l"(p));
    return a;
}
__device__ __forceinline__ void cpa16(uint32_t dst, const void* src) {
    asm volatile("cp.async.cg.shared.global [%0], [%1], 16;"
                 :: "r"(dst), "l"(src) : "memory");
}
__device__ __forceinline__ void mma_bf16(float* c, const uint32_t* a, const uint32_t* b) {
    asm volatile(
        "mma.sync.aligned.m16n8k16.row.col.f32.bf16.bf16.f32 "
        "{%0,%1,%2,%3}, {%4,%5,%6,%7}, {%8,%9}, {%0,%1,%2,%3};"
        : "+f"(c[0]), "+f"(c[1]), "+f"(c[2]), "+f"(c[3])
        : "r"(a[0]), "r"(a[1]), "r"(a[2]), "r"(a[3]), "r"(b[0]), "r"(b[1]));
}
__device__ __forceinline__ void ldm_x4(uint32_t* r, uint32_t addr) {
    asm volatile("ldmatrix.sync.aligned.m8n8.x4.shared.b16 {%0,%1,%2,%3}, [%4];"
                 : "=r"(r[0]), "=r"(r[1]), "=r"(r[2]), "=r"(r[3]) : "r"(addr));
}
__device__ __forceinline__ void ldm_x2(uint32_t* r, uint32_t addr) {
    asm volatile("ldmatrix.sync.aligned.m8n8.x2.shared.b16 {%0,%1}, [%2];"
                 : "=r"(r[0]), "=r"(r[1]) : "r"(addr));
}

// ---------------------------------------------------------------------------
// Split fp32 -> bf16 hi/lo
// ---------------------------------------------------------------------------
__global__ void split_kernel(const float* __restrict__ src,
                             __nv_bfloat16* __restrict__ hi,
                             __nv_bfloat16* __restrict__ lo, int n)
{
    const int i = (blockIdx.x * blockDim.x + threadIdx.x) * 4;
    if (i >= n) return;
    const float4 v = *reinterpret_cast<const float4*>(src + i);
    __nv_bfloat16 h[4], l[4];
    const float f[4] = {v.x, v.y, v.z, v.w};
    #pragma unroll
    for (int j = 0; j < 4; ++j) {
        h[j] = __float2bfloat16(f[j]);
        l[j] = __float2bfloat16(f[j] - __bfloat162float(h[j]));
    }
    *reinterpret_cast<__nv_bfloat162*>(hi + i)     = __nv_bfloat162(h[0], h[1]);
    *reinterpret_cast<__nv_bfloat162*>(hi + i + 2) = __nv_bfloat162(h[2], h[3]);
    *reinterpret_cast<__nv_bfloat162*>(lo + i)     = __nv_bfloat162(l[0], l[1]);
    *reinterpret_cast<__nv_bfloat162*>(lo + i + 2) = __nv_bfloat162(l[2], l[3]);
}

// ---------------------------------------------------------------------------
// Split-bf16 tensor-core GEMM (HMMA), as in R7 (passing)
// ---------------------------------------------------------------------------
#define TSTAGE 40960
#define TROW   80

__global__ __launch_bounds__(256, 2)
void gemm_mma(const __nv_bfloat16* __restrict__ Ahi,
              const __nv_bfloat16* __restrict__ Alo,
              const __nv_bfloat16* __restrict__ Bhi,
              const __nv_bfloat16* __restrict__ Blo,
              float* __restrict__ C, int K, int ldc)
{
    extern __shared__ char smem[];
    const uint32_t sm0 = smem_u32(smem);
    const int tid  = threadIdx.x;
    const int wid  = tid >> 5;
    const int lane = tid & 31;
    const int wm   = wid >> 2;
    const int wn   = wid & 3;
    const int bm   = blockIdx.y * 128;
    const int bn   = blockIdx.x * 128;
    const int g    = lane >> 2;
    const int q    = lane & 3;

    const uint32_t aoffL = (uint32_t)(lane & 15) * TROW + (uint32_t)(lane >> 4) * 16;
    const uint32_t boffL = (uint32_t)(lane & 7) * TROW + (uint32_t)((lane >> 3) & 1) * 16;

    float acc[4][4][4] = {};

    auto stage_load = [&](int kt, int s) {
        const uint32_t sb = sm0 + s * TSTAGE;
        #pragma unroll
        for (int i = 0; i < 2; ++i) {
            const int idx = tid + 256 * i;
            const int row = idx >> 2;
            const int c4  = idx & 3;
            const uint32_t so = (uint32_t)row * TROW + c4 * 16;
            const size_t goA = (size_t)(bm + row) * K + kt + c4 * 8;
            const size_t goB = (size_t)(bn + row) * K + kt + c4 * 8;
            cpa16(sb + so,         Ahi + goA);
            cpa16(sb + 10240 + so, Alo + goA);
            cpa16(sb + 20480 + so, Bhi + goB);
            cpa16(sb + 30720 + so, Blo + goB);
        }
        asm volatile("cp.async.commit_group;" ::: "memory");
    };

    stage_load(0, 0);

    const int nt_iters = K / 32;
    for (int t = 0; t < nt_iters; ++t) {
        asm volatile("cp.async.wait_group 0;" ::: "memory");
        __syncthreads();
        if (t + 1 < nt_iters) stage_load((t + 1) * 32, (t + 1) & 1);

        const uint32_t stg = sm0 + (t & 1) * TSTAGE;
        #pragma unroll
        for (int ks = 0; ks < 2; ++ks) {
            uint32_t a_hi[4][4], a_lo[4][4];
            #pragma unroll
            for (int mt = 0; mt < 4; ++mt) {
                const uint32_t ab = stg + (uint32_t)(wm * 64 + mt * 16) * TROW
                                        + ks * 32 + aoffL;
                ldm_x4(a_hi[mt], ab);
                ldm_x4(a_lo[mt], ab + 10240);
            }
            #pragma unroll
            for (int nt = 0; nt < 4; ++nt) {
                const uint32_t bb = stg + 20480 + (uint32_t)(wn * 32 + nt * 8) * TROW
                                        + ks * 32 + boffL;
                uint32_t bh[2], bl2[2];
                ldm_x2(bh,  bb);
                ldm_x2(bl2, bb + 10240);
                #pragma unroll
                for (int mt = 0; mt < 4; ++mt) {
                    mma_bf16(acc[mt][nt], a_hi[mt], bh);
                    mma_bf16(acc[mt][nt], a_hi[mt], bl2);
                    mma_bf16(acc[mt][nt], a_lo[mt], bh);
                }
            }
        }
        __syncthreads();
    }

    #pragma unroll
    for (int mt = 0; mt < 4; ++mt) {
        const int r0 = bm + wm * 64 + mt * 16 + g;
        #pragma unroll
        for (int nt = 0; nt < 4; ++nt) {
            const int c0 = bn + wn * 32 + nt * 8 + q * 2;
            *reinterpret_cast<float2*>(&C[(size_t)r0 * ldc + c0]) =
                make_float2(acc[mt][nt][0], acc[mt][nt][1]);
            *reinterpret_cast<float2*>(&C[(size_t)(r0 + 8) * ldc + c0]) =
                make_float2(acc[mt][nt][2], acc[mt][nt][3]);
        }
    }
}

// ---------------------------------------------------------------------------
// Packed f32x2 helpers
// ---------------------------------------------------------------------------
__device__ __forceinline__ unsigned long long pk2(float lo, float hi) {
    unsigned long long r;
    asm("mov.b64 %0, {%1, %2};" : "=l"(r) : "f"(lo), "f"(hi));
    return r;
}
__device__ __forceinline__ void fma2(unsigned long long& d,
                                     unsigned long long a, unsigned long long b) {
    asm("fma.rn.f32x2 %0, %1, %2, %0;" : "+l"(d) : "l"(a), "l"(b));
}
__device__ __forceinline__ float2 upk2(unsigned long long v) {
    float2 f;
    asm("mov.b64 {%0, %1}, %2;" : "=f"(f.x), "=f"(f.y) : "l"(v));
    return f;
}

// ---------------------------------------------------------------------------
// Scalar NT SGEMM (f32x2, double-buffered) — GEMM2/GEMM3
// ---------------------------------------------------------------------------
template<int BM, int BN, int BK, int TM, int TN, int EPI>
__global__ __launch_bounds__((BM / TM) * (BN / TN), 2)
void gemm_nt(const float* __restrict__ A, int lda,
             const float* __restrict__ Bw, int ldb,
             float* __restrict__ C, int ldc,
             int M, int Nn, int K,
             const float* __restrict__ bias)
{
    constexpr int THREADS = (BM / TM) * (BN / TN);
    constexpr int VPR     = BK / 4;
    constexpr int RS      = THREADS / VPR;
    constexpr int AR      = BM / RS;
    constexpr int BR      = BN / RS;
    constexpr int LDA_S   = BM + 4;
    constexpr int LDB_S   = BN + 4;

    __shared__ float As[2][BK][LDA_S];
    __shared__ float Bs[2][BK][LDB_S];

    const int tid = threadIdx.x;
    const int tx  = tid % (BN / TN);
    const int ty  = tid / (BN / TN);
    const int bm  = blockIdx.y * BM;
    const int bn  = blockIdx.x * BN;
    const int lr  = tid / VPR;
    const int lc  = (tid % VPR) * 4;

    unsigned long long acc[TM][TN / 2] = {};
    float4 ar[AR], br[BR];

    auto ldg = [&](int kt) {
        #pragma unroll
        for (int i = 0; i < AR; ++i)
            ar[i] = *reinterpret_cast<const float4*>(
                &A[(size_t)(bm + i * RS + lr) * lda + kt + lc]);
        #pragma unroll
        for (int i = 0; i < BR; ++i) {
            const int n = bn + i * RS + lr;
            br[i] = (n < Nn)
                  ? *reinterpret_cast<const float4*>(&Bw[(size_t)n * ldb + kt + lc])
                  : make_float4(0.f, 0.f, 0.f, 0.f);
        }
    };
    auto sts = [&](int s) {
        #pragma unroll
        for (int i = 0; i < AR; ++i) {
            As[s][lc + 0][i * RS + lr] = ar[i].x;
            As[s][lc + 1][i * RS + lr] = ar[i].y;
            As[s][lc + 2][i * RS + lr] = ar[i].z;
            As[s][lc + 3][i * RS + lr] = ar[i].w;
        }
        #pragma unroll
        for (int i = 0; i < BR; ++i) {
            Bs[s][lc + 0][i * RS + lr] = br[i].x;
            Bs[s][lc + 1][i * RS + lr] = br[i].y;
            Bs[s][lc + 2][i * RS + lr] = br[i].z;
            Bs[s][lc + 3][i * RS + lr] = br[i].w;
        }
    };

    ldg(0);
    sts(0);
    __syncthreads();

    const int nt = K / BK;
    for (int t = 0; t < nt; ++t) {
        const int cur = t & 1;
        if (t + 1 < nt) ldg((t + 1) * BK);

        #pragma unroll
        for (int k = 0; k < BK; ++k) {
            float4 af[TM / 4], bf[TN / 4];
            #pragma unroll
            for (int i = 0; i < TM / 4; ++i)
                af[i] = *reinterpret_cast<const float4*>(&As[cur][k][ty * TM + 4 * i]);
            #pragma unroll
            for (int j = 0; j < TN / 4; ++j)
                bf[j] = *reinterpret_cast<const float4*>(&Bs[cur][k][tx * TN + 4 * j]);

            unsigned long long bp[TN / 2];
            #pragma unroll
            for (int j = 0; j < TN / 4; ++j) {
                bp[2 * j]     = pk2(bf[j].x, bf[j].y);
                bp[2 * j + 1] = pk2(bf[j].z, bf[j].w);
            }
            const float* afs = reinterpret_cast<const float*>(af);
            #pragma unroll
            for (int i = 0; i < TM; ++i) {
                const unsigned long long a2 = pk2(afs[i], afs[i]);
                #pragma unroll
                for (int j = 0; j < TN / 2; ++j)
                    fma2(acc[i][j], a2, bp[j]);
            }
        }

        if (t + 1 < nt) sts((t + 1) & 1);
        __syncthreads();
    }

    #pragma unroll
    for (int i = 0; i < TM; ++i) {
        const int row = bm + ty * TM + i;
        #pragma unroll
        for (int j = 0; j < TN / 2; ++j) {
            const int col = bn + tx * TN + 2 * j;
            if (col < Nn) {
                float2 p = upk2(acc[i][j]);
                if (EPI == 1) {
                    p.x += bias[col];
                    p.x = (p.x > 20.f) ? p.x : log1pf(__expf(p.x));
                    p.y += bias[col + 1];
                    p.y = (p.y > 20.f) ? p.y : log1pf(__expf(p.y));
                }
                *reinterpret_cast<float2*>(&C[(size_t)row * ldc + col]) = p;
            }
        }
    }
}

// ---------------------------------------------------------------------------
// Depthwise causal conv (K=4) + bias + silu
// ---------------------------------------------------------------------------
__global__ void conv_silu_kernel(const float* __restrict__ xz,
                                 const float* __restrict__ conv_w,
                                 const float* __restrict__ conv_b,
                                 float* __restrict__ xc)
{
    const int d = blockIdx.x * blockDim.x + threadIdx.x;
    const int l = blockIdx.y;
    const int b = blockIdx.z;

    float accv = conv_b[d];
    #pragma unroll
    for (int k = 0; k < Kc; ++k) {
        const int ls = l - (Kc - 1) + k;
        if (ls >= 0)
            accv = fmaf(xz[((size_t)b * Lc + ls) * TWO_DIc + d],
                        conv_w[d * Kc + k], accv);
    }
    const float s = accv / (1.f + __expf(-accv));
    xc[((size_t)b * Lc + l) * DIc + d] = s;
}

// ---------------------------------------------------------------------------
// Chunk-parallel selective scan. Chunk is the SLOWEST gid index so the 16
// groups within a block cover consecutive d -> dt/xc/z loads coalesce
// exactly like the (measured-fine) R7 serial scan.
// Phase 1: local scan from h=0; store end state S and decay product P.
// ---------------------------------------------------------------------------
__global__ void scan_p1(const float* __restrict__ dt,
                        const float* __restrict__ dbl,
                        const float* __restrict__ xc,
                        const float* __restrict__ A_log,
                        float* __restrict__ S, float* __restrict__ P)
{
    const int gid  = blockIdx.x * (blockDim.x >> 4) + (threadIdx.x >> 4);
    const int lane = threadIdx.x & 15;
    const int c = gid >> 13;           // / (Bc*DIc)
    const int b = (gid >> 11) & 3;
    const int d = gid & (DIc - 1);

    const float An = -__expf(A_log[d * Nc + lane]);
    float h = 0.f, p = 1.f;

    const size_t base = (size_t)b * Lc + (size_t)c * CL;
    const float* dt_p = dt  + base * DIc + d;
    const float* xc_p = xc  + base * DIc + d;
    const float* bb_p = dbl + base * RNc + Rc + lane;

    for (int l = 0; l < CL; ++l) {
        const float dtv = dt_p[(size_t)l * DIc];
        const float xcv = xc_p[(size_t)l * DIc];
        const float Bn  = bb_p[(size_t)l * RNc];
        const float dA  = __expf(dtv * An);
        h = fmaf(dA, h, dtv * Bn * xcv);
        p *= dA;
    }
    const size_t o = (((size_t)b * DIc + d) * CH + c) * Nc + lane;
    S[o] = h;
    P[o] = p;
}

// Phase 2: per (b,d) group: sequential combine over CH chunks; store each
//          chunk's true start state Hst.
__global__ void scan_p2(const float* __restrict__ S,
                        const float* __restrict__ P,
                        float* __restrict__ Hst)
{
    const int gid  = blockIdx.x * (blockDim.x >> 4) + (threadIdx.x >> 4);
    const int lane = threadIdx.x & 15;
    const size_t base = (size_t)gid * CH * Nc + lane;

    float H = 0.f;
    #pragma unroll
    for (int c = 0; c < CH; ++c) {
        Hst[base + c * Nc] = H;
        H = fmaf(P[base + c * Nc], H, S[base + c * Nc]);
    }
}

// Phase 3: re-scan from true start state; emit y (bf16 hi/lo)
__global__ void scan_p3(const float* __restrict__ dt,
                        const float* __restrict__ dbl,
                        const float* __restrict__ xc,
                        const float* __restrict__ xz,
                        const float* __restrict__ A_log,
                        const float* __restrict__ D_param,
                        const float* __restrict__ Hst,
                        __nv_bfloat16* __restrict__ yhi,
                        __nv_bfloat16* __restrict__ ylo)
{
    const int gid  = blockIdx.x * (blockDim.x >> 4) + (threadIdx.x >> 4);
    const int lane = threadIdx.x & 15;
    const int c = gid >> 13;
    const int b = (gid >> 11) & 3;
    const int d = gid & (DIc - 1);

    const float An = -__expf(A_log[d * Nc + lane]);
    const float Dd = D_param[d];
    float h = Hst[(((size_t)b * DIc + d) * CH + c) * Nc + lane];

    const size_t base = (size_t)b * Lc + (size_t)c * CL;
    const float* dt_p = dt  + base * DIc + d;
    const float* xc_p = xc  + base * DIc + d;
    const float* z_p  = xz  + base * TWO_DIc + DIc + d;
    const float* bc_p = dbl + base * RNc + Rc;
    __nv_bfloat16* yh_p = yhi + base * DIc + d;
    __nv_bfloat16* yl_p = ylo + base * DIc + d;

    for (int l = 0; l < CL; ++l) {
        const float dtv = dt_p[(size_t)l * DIc];
        const float xcv = xc_p[(size_t)l * DIc];
        const float Bn  = bc_p[(size_t)l * RNc + lane];
        const float Cn  = bc_p[(size_t)l * RNc + Nc + lane];

        const float dA = __expf(dtv * An);
        h = fmaf(dA, h, dtv * Bn * xcv);

        float v = h * Cn;
        v += __shfl_xor_sync(0xffffffffu, v, 8);
        v += __shfl_xor_sync(0xffffffffu, v, 4);
        v += __shfl_xor_sync(0xffffffffu, v, 2);
        v += __shfl_xor_sync(0xffffffffu, v, 1);

        if (lane == 0) {
            const float zv = z_p[(size_t)l * TWO_DIc];
            float yv = (v + xcv * Dd) * (zv / (1.f + __expf(-zv)));
            const __nv_bfloat16 hh = __float2bfloat16(yv);
            yh_p[(size_t)l * DIc] = hh;
            yl_p[(size_t)l * DIc] = __float2bfloat16(yv - __bfloat162float(hh));
        }
    }
}

// ---------------------------------------------------------------------------
extern "C" void kernel_launch(void* const* d_in, const int* in_sizes, int n_in,
                              void* d_out, int out_size)
{
    const float* x       = (const float*)d_in[0];
    const float* W_in    = (const float*)d_in[1];
    const float* conv_w  = (const float*)d_in[2];
    const float* conv_b  = (const float*)d_in[3];
    const float* W_xproj = (const float*)d_in[4];
    const float* W_dt    = (const float*)d_in[5];
    const float* dt_bias = (const float*)d_in[6];
    const float* A_log   = (const float*)d_in[7];
    const float* D_param = (const float*)d_in[8];
    const float* W_out   = (const float*)d_in[9];
    float* out = (float*)d_out;

    float *xz, *xc, *dbl, *dtb, *Sb, *Pb, *Hb;
    __nv_bfloat16 *xhi, *xlo, *wihi, *wilo, *yhi, *ylo, *wohi, *wolo;
    cudaGetSymbolAddress((void**)&xz,   g_xz);
    cudaGetSymbolAddress((void**)&xc,   g_xc);
    cudaGetSymbolAddress((void**)&dbl,  g_dbl);
    cudaGetSymbolAddress((void**)&dtb,  g_dt);
    cudaGetSymbolAddress((void**)&Sb,   g_S);
    cudaGetSymbolAddress((void**)&Pb,   g_P);
    cudaGetSymbolAddress((void**)&Hb,   g_H);
    cudaGetSymbolAddress((void**)&xhi,  g_xhi);
    cudaGetSymbolAddress((void**)&xlo,  g_xlo);
    cudaGetSymbolAddress((void**)&wihi, g_wihi);
    cudaGetSymbolAddress((void**)&wilo, g_wilo);
    cudaGetSymbolAddress((void**)&yhi,  g_yhi);
    cudaGetSymbolAddress((void**)&ylo,  g_ylo);
    cudaGetSymbolAddress((void**)&wohi, g_wohi);
    cudaGetSymbolAddress((void**)&wolo, g_wolo);

    const int M = Bc * Lc;  // 8192
    const int TENSOR_SMEM = 2 * TSTAGE;

    cudaFuncSetAttribute(gemm_mma,
                         cudaFuncAttributeMaxDynamicSharedMemorySize, TENSOR_SMEM);

    // Split inputs to bf16 hi/lo
    split_kernel<<<(M * Dc / 4 + 255) / 256, 256>>>(x, xhi, xlo, M * Dc);
    split_kernel<<<(TWO_DIc * Dc / 4 + 255) / 256, 256>>>(W_in, wihi, wilo, TWO_DIc * Dc);
    split_kernel<<<(Dc * DIc / 4 + 255) / 256, 256>>>(W_out, wohi, wolo, Dc * DIc);

    // GEMM1 (tensor): xz[M,4096] = x @ W_in^T
    gemm_mma<<<dim3(TWO_DIc / 128, M / 128), 256, TENSOR_SMEM>>>(
        xhi, xlo, wihi, wilo, xz, Dc, TWO_DIc);

    // Depthwise causal conv + silu -> xc
    conv_silu_kernel<<<dim3(DIc / 256, Lc, Bc), 256>>>(xz, conv_w, conv_b, xc);

    // GEMM2 (scalar): dbl[M,96] = xc @ W_xproj^T
    gemm_nt<32, 128, 16, 4, 8, 0><<<dim3(1, M / 32), 128>>>(
        xc, DIc, W_xproj, DIc, dbl, RNc, M, RNc, DIc, nullptr);

    // GEMM3 (scalar): dt[M,2048] = softplus(dbl[:, :64] @ W_dt^T + dt_bias)
    gemm_nt<128, 128, 16, 8, 8, 1><<<dim3(DIc / 128, M / 128), 256>>>(
        dbl, RNc, W_dt, Rc, dtb, DIc, M, DIc, Rc, dt_bias);

    // Chunk-parallel scan (chunk = slowest index -> coalesced)
    scan_p1<<<(Bc * DIc * CH) / 16, 256>>>(dtb, dbl, xc, A_log, Sb, Pb);
    scan_p2<<<(Bc * DIc) / 16, 256>>>(Sb, Pb, Hb);
    scan_p3<<<(Bc * DIc * CH) / 16, 256>>>(dtb, dbl, xc, xz, A_log, D_param,
                                           Hb, yhi, ylo);

    // GEMM4 (tensor): out[M,1024] = y @ W_out^T
    gemm_mma<<<dim3(Dc / 128, M / 128), 256, TENSOR_SMEM>>>(
        yhi, ylo, wohi, wolo, out, DIc, Dc);
}

// round 12
// speedup vs baseline: 1.2495x; 1.2212x over previous
#include <cuda_runtime.h>
#include <cuda_bf16.h>
#include <math.h>
#include <stdint.h>

// Problem constants
#define Bc      4
#define Lc      2048
#define Dc      1024
#define DIc     2048
#define TWO_DIc 4096
#define Nc      16
#define Kc      4
#define Rc      64
#define RNc     96    // R + 2N

// fp32 scratch
__device__ float g_xz [(size_t)Bc * Lc * TWO_DIc];
__device__ float g_xc [(size_t)Bc * Lc * DIc];
__device__ float g_dbl[(size_t)Bc * Lc * RNc];
__device__ float g_dt [(size_t)Bc * Lc * DIc];

// bf16 split scratch (hi/lo)
__device__ __nv_bfloat16 g_xhi [(size_t)Bc * Lc * Dc];
__device__ __nv_bfloat16 g_xlo [(size_t)Bc * Lc * Dc];
__device__ __nv_bfloat16 g_wihi[(size_t)TWO_DIc * Dc];
__device__ __nv_bfloat16 g_wilo[(size_t)TWO_DIc * Dc];
__device__ __nv_bfloat16 g_yhi [(size_t)Bc * Lc * DIc];
__device__ __nv_bfloat16 g_ylo [(size_t)Bc * Lc * DIc];
__device__ __nv_bfloat16 g_wohi[(size_t)Dc * DIc];
__device__ __nv_bfloat16 g_wolo[(size_t)Dc * DIc];

// ---------------------------------------------------------------------------
// Helpers
// ---------------------------------------------------------------------------
__device__ __forceinline__ uint32_t smem_u32(const void* p) {
    uint32_t a;
    asm("{ .reg .u64 t; cvta.to.shared.u64 t, %1; cvt.u32.u64 %0, t; }"
        : "=r"(a) : "l"(p));
    return a;
}
__device__ __forceinline__ void cpa16(uint32_t dst, const void* src) {
    asm volatile("cp.async.cg.shared.global [%0], [%1], 16;"
                 :: "r"(dst), "l"(src) : "memory");
}
__device__ __forceinline__ void mma_bf16(float* c, const uint32_t* a, const uint32_t* b) {
    asm volatile(
        "mma.sync.aligned.m16n8k16.row.col.f32.bf16.bf16.f32 "
        "{%0,%1,%2,%3}, {%4,%5,%6,%7}, {%8,%9}, {%0,%1,%2,%3};"
        : "+f"(c[0]), "+f"(c[1]), "+f"(c[2]), "+f"(c[3])
        : "r"(a[0]), "r"(a[1]), "r"(a[2]), "r"(a[3]), "r"(b[0]), "r"(b[1]));
}
__device__ __forceinline__ void ldm_x4(uint32_t* r, uint32_t addr) {
    asm volatile("ldmatrix.sync.aligned.m8n8.x4.shared.b16 {%0,%1,%2,%3}, [%4];"
                 : "=r"(r[0]), "=r"(r[1]), "=r"(r[2]), "=r"(r[3]) : "r"(addr));
}
__device__ __forceinline__ void ldm_x2(uint32_t* r, uint32_t addr) {
    asm volatile("ldmatrix.sync.aligned.m8n8.x2.shared.b16 {%0,%1}, [%2];"
                 : "=r"(r[0]), "=r"(r[1]) : "r"(addr));
}

// ---------------------------------------------------------------------------
// Split fp32 -> bf16 hi/lo
// ---------------------------------------------------------------------------
__global__ void split_kernel(const float* __restrict__ src,
                             __nv_bfloat16* __restrict__ hi,
                             __nv_bfloat16* __restrict__ lo, int n)
{
    const int i = (blockIdx.x * blockDim.x + threadIdx.x) * 4;
    if (i >= n) return;
    const float4 v = *reinterpret_cast<const float4*>(src + i);
    __nv_bfloat16 h[4], l[4];
    const float f[4] = {v.x, v.y, v.z, v.w};
    #pragma unroll
    for (int j = 0; j < 4; ++j) {
        h[j] = __float2bfloat16(f[j]);
        l[j] = __float2bfloat16(f[j] - __bfloat162float(h[j]));
    }
    *reinterpret_cast<__nv_bfloat162*>(hi + i)     = __nv_bfloat162(h[0], h[1]);
    *reinterpret_cast<__nv_bfloat162*>(hi + i + 2) = __nv_bfloat162(h[2], h[3]);
    *reinterpret_cast<__nv_bfloat162*>(lo + i)     = __nv_bfloat162(l[0], l[1]);
    *reinterpret_cast<__nv_bfloat162*>(lo + i + 2) = __nv_bfloat162(l[2], l[3]);
}

// ---------------------------------------------------------------------------
// Split-bf16 tensor-core GEMM (HMMA). Pass loop hoisted outside mt so
// consecutive HMMAs hit different accumulators (RAW distance 4, not 1).
// Per-accumulator accumulation order unchanged (hh -> hl -> lh): results
// are bit-identical to the R7 version.
// ---------------------------------------------------------------------------
#define TSTAGE 40960
#define TROW   80

__global__ __launch_bounds__(256, 2)
void gemm_mma(const __nv_bfloat16* __restrict__ Ahi,
              const __nv_bfloat16* __restrict__ Alo,
              const __nv_bfloat16* __restrict__ Bhi,
              const __nv_bfloat16* __restrict__ Blo,
              float* __restrict__ C, int K, int ldc)
{
    extern __shared__ char smem[];
    const uint32_t sm0 = smem_u32(smem);
    const int tid  = threadIdx.x;
    const int wid  = tid >> 5;
    const int lane = tid & 31;
    const int wm   = wid >> 2;
    const int wn   = wid & 3;
    const int bm   = blockIdx.y * 128;
    const int bn   = blockIdx.x * 128;
    const int g    = lane >> 2;
    const int q    = lane & 3;

    const uint32_t aoffL = (uint32_t)(lane & 15) * TROW + (uint32_t)(lane >> 4) * 16;
    const uint32_t boffL = (uint32_t)(lane & 7) * TROW + (uint32_t)((lane >> 3) & 1) * 16;

    float acc[4][4][4] = {};

    auto stage_load = [&](int kt, int s) {
        const uint32_t sb = sm0 + s * TSTAGE;
        #pragma unroll
        for (int i = 0; i < 2; ++i) {
            const int idx = tid + 256 * i;
            const int row = idx >> 2;
            const int c4  = idx & 3;
            const uint32_t so = (uint32_t)row * TROW + c4 * 16;
            const size_t goA = (size_t)(bm + row) * K + kt + c4 * 8;
            const size_t goB = (size_t)(bn + row) * K + kt + c4 * 8;
            cpa16(sb + so,         Ahi + goA);
            cpa16(sb + 10240 + so, Alo + goA);
            cpa16(sb + 20480 + so, Bhi + goB);
            cpa16(sb + 30720 + so, Blo + goB);
        }
        asm volatile("cp.async.commit_group;" ::: "memory");
    };

    stage_load(0, 0);

    const int nt_iters = K / 32;
    for (int t = 0; t < nt_iters; ++t) {
        asm volatile("cp.async.wait_group 0;" ::: "memory");
        __syncthreads();
        if (t + 1 < nt_iters) stage_load((t + 1) * 32, (t + 1) & 1);

        const uint32_t stg = sm0 + (t & 1) * TSTAGE;
        #pragma unroll
        for (int ks = 0; ks < 2; ++ks) {
            uint32_t a_hi[4][4], a_lo[4][4];
            #pragma unroll
            for (int mt = 0; mt < 4; ++mt) {
                const uint32_t ab = stg + (uint32_t)(wm * 64 + mt * 16) * TROW
                                        + ks * 32 + aoffL;
                ldm_x4(a_hi[mt], ab);
                ldm_x4(a_lo[mt], ab + 10240);
            }
            #pragma unroll
            for (int nt = 0; nt < 4; ++nt) {
                const uint32_t bb = stg + 20480 + (uint32_t)(wn * 32 + nt * 8) * TROW
                                        + ks * 32 + boffL;
                uint32_t bh[2], bl2[2];
                ldm_x2(bh,  bb);
                ldm_x2(bl2, bb + 10240);
                // Pass-major order: consecutive HMMAs use different acc regs.
                #pragma unroll
                for (int mt = 0; mt < 4; ++mt)
                    mma_bf16(acc[mt][nt], a_hi[mt], bh);
                #pragma unroll
                for (int mt = 0; mt < 4; ++mt)
                    mma_bf16(acc[mt][nt], a_hi[mt], bl2);
                #pragma unroll
                for (int mt = 0; mt < 4; ++mt)
                    mma_bf16(acc[mt][nt], a_lo[mt], bh);
            }
        }
        __syncthreads();
    }

    #pragma unroll
    for (int mt = 0; mt < 4; ++mt) {
        const int r0 = bm + wm * 64 + mt * 16 + g;
        #pragma unroll
        for (int nt = 0; nt < 4; ++nt) {
            const int c0 = bn + wn * 32 + nt * 8 + q * 2;
            *reinterpret_cast<float2*>(&C[(size_t)r0 * ldc + c0]) =
                make_float2(acc[mt][nt][0], acc[mt][nt][1]);
            *reinterpret_cast<float2*>(&C[(size_t)(r0 + 8) * ldc + c0]) =
                make_float2(acc[mt][nt][2], acc[mt][nt][3]);
        }
    }
}

// ---------------------------------------------------------------------------
// Packed f32x2 helpers
// ---------------------------------------------------------------------------
__device__ __forceinline__ unsigned long long pk2(float lo, float hi) {
    unsigned long long r;
    asm("mov.b64 %0, {%1, %2};" : "=l"(r) : "f"(lo), "f"(hi));
    return r;
}
__device__ __forceinline__ void fma2(unsigned long long& d,
                                     unsigned long long a, unsigned long long b) {
    asm("fma.rn.f32x2 %0, %1, %2, %0;" : "+l"(d) : "l"(a), "l"(b));
}
__device__ __forceinline__ float2 upk2(unsigned long long v) {
    float2 f;
    asm("mov.b64 {%0, %1}, %2;" : "=f"(f.x), "=f"(f.y) : "l"(v));
    return f;
}

// ---------------------------------------------------------------------------
// Scalar NT SGEMM (f32x2, double-buffered) — GEMM2/GEMM3
// ---------------------------------------------------------------------------
template<int BM, int BN, int BK, int TM, int TN, int EPI>
__global__ __launch_bounds__((BM / TM) * (BN / TN), 2)
void gemm_nt(const float* __restrict__ A, int lda,
             const float* __restrict__ Bw, int ldb,
             float* __restrict__ C, int ldc,
             int M, int Nn, int K,
             const float* __restrict__ bias)
{
    constexpr int THREADS = (BM / TM) * (BN / TN);
    constexpr int VPR     = BK / 4;
    constexpr int RS      = THREADS / VPR;
    constexpr int AR      = BM / RS;
    constexpr int BR      = BN / RS;
    constexpr int LDA_S   = BM + 4;
    constexpr int LDB_S   = BN + 4;

    __shared__ float As[2][BK][LDA_S];
    __shared__ float Bs[2][BK][LDB_S];

    const int tid = threadIdx.x;
    const int tx  = tid % (BN / TN);
    const int ty  = tid / (BN / TN);
    const int bm  = blockIdx.y * BM;
    const int bn  = blockIdx.x * BN;
    const int lr  = tid / VPR;
    const int lc  = (tid % VPR) * 4;

    unsigned long long acc[TM][TN / 2] = {};
    float4 ar[AR], br[BR];

    auto ldg = [&](int kt) {
        #pragma unroll
        for (int i = 0; i < AR; ++i)
            ar[i] = *reinterpret_cast<const float4*>(
                &A[(size_t)(bm + i * RS + lr) * lda + kt + lc]);
        #pragma unroll
        for (int i = 0; i < BR; ++i) {
            const int n = bn + i * RS + lr;
            br[i] = (n < Nn)
                  ? *reinterpret_cast<const float4*>(&Bw[(size_t)n * ldb + kt + lc])
                  : make_float4(0.f, 0.f, 0.f, 0.f);
        }
    };
    auto sts = [&](int s) {
        #pragma unroll
        for (int i = 0; i < AR; ++i) {
            As[s][lc + 0][i * RS + lr] = ar[i].x;
            As[s][lc + 1][i * RS + lr] = ar[i].y;
            As[s][lc + 2][i * RS + lr] = ar[i].z;
            As[s][lc + 3][i * RS + lr] = ar[i].w;
        }
        #pragma unroll
        for (int i = 0; i < BR; ++i) {
            Bs[s][lc + 0][i * RS + lr] = br[i].x;
            Bs[s][lc + 1][i * RS + lr] = br[i].y;
            Bs[s][lc + 2][i * RS + lr] = br[i].z;
            Bs[s][lc + 3][i * RS + lr] = br[i].w;
        }
    };

    ldg(0);
    sts(0);
    __syncthreads();

    const int nt = K / BK;
    for (int t = 0; t < nt; ++t) {
        const int cur = t & 1;
        if (t + 1 < nt) ldg((t + 1) * BK);

        #pragma unroll
        for (int k = 0; k < BK; ++k) {
            float4 af[TM / 4], bf[TN / 4];
            #pragma unroll
            for (int i = 0; i < TM / 4; ++i)
                af[i] = *reinterpret_cast<const float4*>(&As[cur][k][ty * TM + 4 * i]);
            #pragma unroll
            for (int j = 0; j < TN / 4; ++j)
                bf[j] = *reinterpret_cast<const float4*>(&Bs[cur][k][tx * TN + 4 * j]);

            unsigned long long bp[TN / 2];
            #pragma unroll
            for (int j = 0; j < TN / 4; ++j) {
                bp[2 * j]     = pk2(bf[j].x, bf[j].y);
                bp[2 * j + 1] = pk2(bf[j].z, bf[j].w);
            }
            const float* afs = reinterpret_cast<const float*>(af);
            #pragma unroll
            for (int i = 0; i < TM; ++i) {
                const unsigned long long a2 = pk2(afs[i], afs[i]);
                #pragma unroll
                for (int j = 0; j < TN / 2; ++j)
                    fma2(acc[i][j], a2, bp[j]);
            }
        }

        if (t + 1 < nt) sts((t + 1) & 1);
        __syncthreads();
    }

    #pragma unroll
    for (int i = 0; i < TM; ++i) {
        const int row = bm + ty * TM + i;
        #pragma unroll
        for (int j = 0; j < TN / 2; ++j) {
            const int col = bn + tx * TN + 2 * j;
            if (col < Nn) {
                float2 p = upk2(acc[i][j]);
                if (EPI == 1) {
                    p.x += bias[col];
                    p.x = (p.x > 20.f) ? p.x : log1pf(__expf(p.x));
                    p.y += bias[col + 1];
                    p.y = (p.y > 20.f) ? p.y : log1pf(__expf(p.y));
                }
                *reinterpret_cast<float2*>(&C[(size_t)row * ldc + col]) = p;
            }
        }
    }
}

// ---------------------------------------------------------------------------
// Depthwise causal conv (K=4) + bias + silu
// ---------------------------------------------------------------------------
__global__ void conv_silu_kernel(const float* __restrict__ xz,
                                 const float* __restrict__ conv_w,
                                 const float* __restrict__ conv_b,
                                 float* __restrict__ xc)
{
    const int d = blockIdx.x * blockDim.x + threadIdx.x;
    const int l = blockIdx.y;
    const int b = blockIdx.z;

    float accv = conv_b[d];
    #pragma unroll
    for (int k = 0; k < Kc; ++k) {
        const int ls = l - (Kc - 1) + k;
        if (ls >= 0)
            accv = fmaf(xz[((size_t)b * Lc + ls) * TWO_DIc + d],
                        conv_w[d * Kc + k], accv);
    }
    const float s = accv / (1.f + __expf(-accv));
    xc[((size_t)b * Lc + l) * DIc + d] = s;
}

// ---------------------------------------------------------------------------
// Selective scan (R7 form: serial over L, 2-deep software pipeline);
// emits y as bf16 hi/lo
// ---------------------------------------------------------------------------
__global__ void scan_kernel(const float* __restrict__ dt,
                            const float* __restrict__ dbl,
                            const float* __restrict__ xc,
                            const float* __restrict__ xz,
                            const float* __restrict__ A_log,
                            const float* __restrict__ D_param,
                            __nv_bfloat16* __restrict__ yhi,
                            __nv_bfloat16* __restrict__ ylo)
{
    const int gid  = blockIdx.x * (blockDim.x >> 4) + (threadIdx.x >> 4);
    const int lane = threadIdx.x & 15;
    const int b = gid / DIc;
    const int d = gid % DIc;

    const float An = -__expf(A_log[d * Nc + lane]);
    const float Dd = D_param[d];
    float h = 0.f;

    const float* dt_p = dt  + (size_t)b * Lc * DIc + d;
    const float* xc_p = xc  + (size_t)b * Lc * DIc + d;
    const float* z_p  = xz  + (size_t)b * Lc * TWO_DIc + DIc + d;
    const float* bc_p = dbl + (size_t)b * Lc * RNc + Rc;
    __nv_bfloat16* yh_p = yhi + (size_t)b * Lc * DIc + d;
    __nv_bfloat16* yl_p = ylo + (size_t)b * Lc * DIc + d;

    float dt0 = dt_p[0],       dt1 = dt_p[DIc];
    float xc0 = xc_p[0],       xc1 = xc_p[DIc];
    float B0  = bc_p[lane],    B1  = bc_p[RNc + lane];
    float C0  = bc_p[Nc+lane], C1  = bc_p[RNc + Nc + lane];
    float z0  = z_p[0],        z1  = z_p[TWO_DIc];

    for (int l = 0; l < Lc; l += 2) {
        float dt2 = 0.f, xc2 = 0.f, B2 = 0.f, C2 = 0.f, z2 = 0.f;
        float dt3 = 0.f, xc3 = 0.f, B3 = 0.f, C3 = 0.f, z3 = 0.f;
        if (l + 2 < Lc) {
            dt2 = dt_p[(size_t)(l + 2) * DIc];
            xc2 = xc_p[(size_t)(l + 2) * DIc];
            B2  = bc_p[(size_t)(l + 2) * RNc + lane];
            C2  = bc_p[(size_t)(l + 2) * RNc + Nc + lane];
            z2  = z_p[(size_t)(l + 2) * TWO_DIc];
            dt3 = dt_p[(size_t)(l + 3) * DIc];
            xc3 = xc_p[(size_t)(l + 3) * DIc];
            B3  = bc_p[(size_t)(l + 3) * RNc + lane];
            C3  = bc_p[(size_t)(l + 3) * RNc + Nc + lane];
            z3  = z_p[(size_t)(l + 3) * TWO_DIc];
        }

        // timestep l
        {
            const float dA = __expf(dt0 * An);
            h = fmaf(dA, h, dt0 * B0 * xc0);
            float v = h * C0;
            v += __shfl_xor_sync(0xffffffffu, v, 8);
            v += __shfl_xor_sync(0xffffffffu, v, 4);
            v += __shfl_xor_sync(0xffffffffu, v, 2);
            v += __shfl_xor_sync(0xffffffffu, v, 1);
            if (lane == 0) {
                float yv = (v + xc0 * Dd) * (z0 / (1.f + __expf(-z0)));
                const __nv_bfloat16 hh = __float2bfloat16(yv);
                yh_p[(size_t)l * DIc] = hh;
                yl_p[(size_t)l * DIc] = __float2bfloat16(yv - __bfloat162float(hh));
            }
        }
        // timestep l+1
        {
            const float dA = __expf(dt1 * An);
            h = fmaf(dA, h, dt1 * B1 * xc1);
            float v = h * C1;
            v += __shfl_xor_sync(0xffffffffu, v, 8);
            v += __shfl_xor_sync(0xffffffffu, v, 4);
            v += __shfl_xor_sync(0xffffffffu, v, 2);
            v += __shfl_xor_sync(0xffffffffu, v, 1);
            if (lane == 0) {
                float yv = (v + xc1 * Dd) * (z1 / (1.f + __expf(-z1)));
                const __nv_bfloat16 hh = __float2bfloat16(yv);
                yh_p[(size_t)(l + 1) * DIc] = hh;
                yl_p[(size_t)(l + 1) * DIc] = __float2bfloat16(yv - __bfloat162float(hh));
            }
        }

        dt0 = dt2; xc0 = xc2; B0 = B2; C0 = C2; z0 = z2;
        dt1 = dt3; xc1 = xc3; B1 = B3; C1 = C3; z1 = z3;
    }
}

// ---------------------------------------------------------------------------
extern "C" void kernel_launch(void* const* d_in, const int* in_sizes, int n_in,
                              void* d_out, int out_size)
{
    const float* x       = (const float*)d_in[0];
    const float* W_in    = (const float*)d_in[1];
    const float* conv_w  = (const float*)d_in[2];
    const float* conv_b  = (const float*)d_in[3];
    const float* W_xproj = (const float*)d_in[4];
    const float* W_dt    = (const float*)d_in[5];
    const float* dt_bias = (const float*)d_in[6];
    const float* A_log   = (const float*)d_in[7];
    const float* D_param = (const float*)d_in[8];
    const float* W_out   = (const float*)d_in[9];
    float* out = (float*)d_out;

    float *xz, *xc, *dbl, *dtb;
    __nv_bfloat16 *xhi, *xlo, *wihi, *wilo, *yhi, *ylo, *wohi, *wolo;
    cudaGetSymbolAddress((void**)&xz,   g_xz);
    cudaGetSymbolAddress((void**)&xc,   g_xc);
    cudaGetSymbolAddress((void**)&dbl,  g_dbl);
    cudaGetSymbolAddress((void**)&dtb,  g_dt);
    cudaGetSymbolAddress((void**)&xhi,  g_xhi);
    cudaGetSymbolAddress((void**)&xlo,  g_xlo);
    cudaGetSymbolAddress((void**)&wihi, g_wihi);
    cudaGetSymbolAddress((void**)&wilo, g_wilo);
    cudaGetSymbolAddress((void**)&yhi,  g_yhi);
    cudaGetSymbolAddress((void**)&ylo,  g_ylo);
    cudaGetSymbolAddress((void**)&wohi, g_wohi);
    cudaGetSymbolAddress((void**)&wolo, g_wolo);

    const int M = Bc * Lc;  // 8192
    const int TENSOR_SMEM = 2 * TSTAGE;

    cudaFuncSetAttribute(gemm_mma,
                         cudaFuncAttributeMaxDynamicSharedMemorySize, TENSOR_SMEM);

    // Split inputs to bf16 hi/lo
    split_kernel<<<(M * Dc / 4 + 255) / 256, 256>>>(x, xhi, xlo, M * Dc);
    split_kernel<<<(TWO_DIc * Dc / 4 + 255) / 256, 256>>>(W_in, wihi, wilo, TWO_DIc * Dc);
    split_kernel<<<(Dc * DIc / 4 + 255) / 256, 256>>>(W_out, wohi, wolo, Dc * DIc);

    // GEMM1 (tensor): xz[M,4096] = x @ W_in^T
    gemm_mma<<<dim3(TWO_DIc / 128, M / 128), 256, TENSOR_SMEM>>>(
        xhi, xlo, wihi, wilo, xz, Dc, TWO_DIc);

    // Depthwise causal conv + silu -> xc
    conv_silu_kernel<<<dim3(DIc / 256, Lc, Bc), 256>>>(xz, conv_w, conv_b, xc);

    // GEMM2 (scalar): dbl[M,96] = xc @ W_xproj^T
    gemm_nt<32, 128, 16, 4, 8, 0><<<dim3(1, M / 32), 128>>>(
        xc, DIc, W_xproj, DIc, dbl, RNc, M, RNc, DIc, nullptr);

    // GEMM3 (scalar): dt[M,2048] = softplus(dbl[:, :64] @ W_dt^T + dt_bias)
    gemm_nt<128, 128, 16, 8, 8, 1><<<dim3(DIc / 128, M / 128), 256>>>(
        dbl, RNc, W_dt, Rc, dtb, DIc, M, DIc, Rc, dt_bias);

    // Selective scan -> y (bf16 hi/lo)
    scan_kernel<<<(Bc * DIc) / 16, 256>>>(dtb, dbl, xc, xz, A_log, D_param, yhi, ylo);

    // GEMM4 (tensor): out[M,1024] = y @ W_out^T
    gemm_mma<<<dim3(Dc / 128, M / 128), 256, TENSOR_SMEM>>>(
        yhi, ylo, wohi, wolo, out, DIc, Dc);
}

// round 13
// speedup vs baseline: 1.2829x; 1.0268x over previous
#include <cuda_runtime.h>
#include <cuda_bf16.h>
#include <math.h>
#include <stdint.h>

// Problem constants
#define Bc      4
#define Lc      2048
#define Dc      1024
#define DIc     2048
#define TWO_DIc 4096
#define Nc      16
#define Kc      4
#define Rc      64
#define RNc     96    // R + 2N

// fp32 scratch
__device__ float g_xz [(size_t)Bc * Lc * TWO_DIc];
__device__ float g_xc [(size_t)Bc * Lc * DIc];
__device__ float g_dbl[(size_t)Bc * Lc * RNc];
__device__ float g_dt [(size_t)Bc * Lc * DIc];

// bf16 split scratch (hi/lo)
__device__ __nv_bfloat16 g_xhi [(size_t)Bc * Lc * Dc];
__device__ __nv_bfloat16 g_xlo [(size_t)Bc * Lc * Dc];
__device__ __nv_bfloat16 g_wihi[(size_t)TWO_DIc * Dc];
__device__ __nv_bfloat16 g_wilo[(size_t)TWO_DIc * Dc];
__device__ __nv_bfloat16 g_yhi [(size_t)Bc * Lc * DIc];
__device__ __nv_bfloat16 g_ylo [(size_t)Bc * Lc * DIc];
__device__ __nv_bfloat16 g_wohi[(size_t)Dc * DIc];
__device__ __nv_bfloat16 g_wolo[(size_t)Dc * DIc];

// ---------------------------------------------------------------------------
// Helpers
// ---------------------------------------------------------------------------
__device__ __forceinline__ uint32_t smem_u32(const void* p) {
    uint32_t a;
    asm("{ .reg .u64 t; cvta.to.shared.u64 t, %1; cvt.u32.u64 %0, t; }"
        : "=r"(a) : "l"(p));
    return a;
}
__device__ __forceinline__ void cpa16(uint32_t dst, const void* src) {
    asm volatile("cp.async.cg.shared.global [%0], [%1], 16;"
                 :: "r"(dst), "l"(src) : "memory");
}
__device__ __forceinline__ void mma_bf16(float* c, const uint32_t* a, const uint32_t* b) {
    asm volatile(
        "mma.sync.aligned.m16n8k16.row.col.f32.bf16.bf16.f32 "
        "{%0,%1,%2,%3}, {%4,%5,%6,%7}, {%8,%9}, {%0,%1,%2,%3};"
        : "+f"(c[0]), "+f"(c[1]), "+f"(c[2]), "+f"(c[3])
        : "r"(a[0]), "r"(a[1]), "r"(a[2]), "r"(a[3]), "r"(b[0]), "r"(b[1]));
}
__device__ __forceinline__ void ldm_x4(uint32_t* r, uint32_t addr) {
    asm volatile("ldmatrix.sync.aligned.m8n8.x4.shared.b16 {%0,%1,%2,%3}, [%4];"
                 : "=r"(r[0]), "=r"(r[1]), "=r"(r[2]), "=r"(r[3]) : "r"(addr));
}
__device__ __forceinline__ void ldm_x2(uint32_t* r, uint32_t addr) {
    asm volatile("ldmatrix.sync.aligned.m8n8.x2.shared.b16 {%0,%1}, [%2];"
                 : "=r"(r[0]), "=r"(r[1]) : "r"(addr));
}

// ---------------------------------------------------------------------------
// Split fp32 -> bf16 hi/lo
// ---------------------------------------------------------------------------
__global__ void split_kernel(const float* __restrict__ src,
                             __nv_bfloat16* __restrict__ hi,
                             __nv_bfloat16* __restrict__ lo, int n)
{
    const int i = (blockIdx.x * blockDim.x + threadIdx.x) * 4;
    if (i >= n) return;
    const float4 v = *reinterpret_cast<const float4*>(src + i);
    __nv_bfloat16 h[4], l[4];
    const float f[4] = {v.x, v.y, v.z, v.w};
    #pragma unroll
    for (int j = 0; j < 4; ++j) {
        h[j] = __float2bfloat16(f[j]);
        l[j] = __float2bfloat16(f[j] - __bfloat162float(h[j]));
    }
    *reinterpret_cast<__nv_bfloat162*>(hi + i)     = __nv_bfloat162(h[0], h[1]);
    *reinterpret_cast<__nv_bfloat162*>(hi + i + 2) = __nv_bfloat162(h[2], h[3]);
    *reinterpret_cast<__nv_bfloat162*>(lo + i)     = __nv_bfloat162(l[0], l[1]);
    *reinterpret_cast<__nv_bfloat162*>(lo + i + 2) = __nv_bfloat162(l[2], l[3]);
}

// ---------------------------------------------------------------------------
// Split-bf16 tensor-core GEMM (HMMA) — as R12 (passing)
// ---------------------------------------------------------------------------
#define TSTAGE 40960
#define TROW   80

__global__ __launch_bounds__(256, 2)
void gemm_mma(const __nv_bfloat16* __restrict__ Ahi,
              const __nv_bfloat16* __restrict__ Alo,
              const __nv_bfloat16* __restrict__ Bhi,
              const __nv_bfloat16* __restrict__ Blo,
              float* __restrict__ C, int K, int ldc)
{
    extern __shared__ char smem[];
    const uint32_t sm0 = smem_u32(smem);
    const int tid  = threadIdx.x;
    const int wid  = tid >> 5;
    const int lane = tid & 31;
    const int wm   = wid >> 2;
    const int wn   = wid & 3;
    const int bm   = blockIdx.y * 128;
    const int bn   = blockIdx.x * 128;
    const int g    = lane >> 2;
    const int q    = lane & 3;

    const uint32_t aoffL = (uint32_t)(lane & 15) * TROW + (uint32_t)(lane >> 4) * 16;
    const uint32_t boffL = (uint32_t)(lane & 7) * TROW + (uint32_t)((lane >> 3) & 1) * 16;

    float acc[4][4][4] = {};

    auto stage_load = [&](int kt, int s) {
        const uint32_t sb = sm0 + s * TSTAGE;
        #pragma unroll
        for (int i = 0; i < 2; ++i) {
            const int idx = tid + 256 * i;
            const int row = idx >> 2;
            const int c4  = idx & 3;
            const uint32_t so = (uint32_t)row * TROW + c4 * 16;
            const size_t goA = (size_t)(bm + row) * K + kt + c4 * 8;
            const size_t goB = (size_t)(bn + row) * K + kt + c4 * 8;
            cpa16(sb + so,         Ahi + goA);
            cpa16(sb + 10240 + so, Alo + goA);
            cpa16(sb + 20480 + so, Bhi + goB);
            cpa16(sb + 30720 + so, Blo + goB);
        }
        asm volatile("cp.async.commit_group;" ::: "memory");
    };

    stage_load(0, 0);

    const int nt_iters = K / 32;
    for (int t = 0; t < nt_iters; ++t) {
        asm volatile("cp.async.wait_group 0;" ::: "memory");
        __syncthreads();
        if (t + 1 < nt_iters) stage_load((t + 1) * 32, (t + 1) & 1);

        const uint32_t stg = sm0 + (t & 1) * TSTAGE;
        #pragma unroll
        for (int ks = 0; ks < 2; ++ks) {
            uint32_t a_hi[4][4], a_lo[4][4];
            #pragma unroll
            for (int mt = 0; mt < 4; ++mt) {
                const uint32_t ab = stg + (uint32_t)(wm * 64 + mt * 16) * TROW
                                        + ks * 32 + aoffL;
                ldm_x4(a_hi[mt], ab);
                ldm_x4(a_lo[mt], ab + 10240);
            }
            #pragma unroll
            for (int nt = 0; nt < 4; ++nt) {
                const uint32_t bb = stg + 20480 + (uint32_t)(wn * 32 + nt * 8) * TROW
                                        + ks * 32 + boffL;
                uint32_t bh[2], bl2[2];
                ldm_x2(bh,  bb);
                ldm_x2(bl2, bb + 10240);
                #pragma unroll
                for (int mt = 0; mt < 4; ++mt)
                    mma_bf16(acc[mt][nt], a_hi[mt], bh);
                #pragma unroll
                for (int mt = 0; mt < 4; ++mt)
                    mma_bf16(acc[mt][nt], a_hi[mt], bl2);
                #pragma unroll
                for (int mt = 0; mt < 4; ++mt)
                    mma_bf16(acc[mt][nt], a_lo[mt], bh);
            }
        }
        __syncthreads();
    }

    #pragma unroll
    for (int mt = 0; mt < 4; ++mt) {
        const int r0 = bm + wm * 64 + mt * 16 + g;
        #pragma unroll
        for (int nt = 0; nt < 4; ++nt) {
            const int c0 = bn + wn * 32 + nt * 8 + q * 2;
            *reinterpret_cast<float2*>(&C[(size_t)r0 * ldc + c0]) =
                make_float2(acc[mt][nt][0], acc[mt][nt][1]);
            *reinterpret_cast<float2*>(&C[(size_t)(r0 + 8) * ldc + c0]) =
                make_float2(acc[mt][nt][2], acc[mt][nt][3]);
        }
    }
}

// ---------------------------------------------------------------------------
// Packed f32x2 helpers
// ---------------------------------------------------------------------------
__device__ __forceinline__ unsigned long long pk2(float lo, float hi) {
    unsigned long long r;
    asm("mov.b64 %0, {%1, %2};" : "=l"(r) : "f"(lo), "f"(hi));
    return r;
}
__device__ __forceinline__ void fma2(unsigned long long& d,
                                     unsigned long long a, unsigned long long b) {
    asm("fma.rn.f32x2 %0, %1, %2, %0;" : "+l"(d) : "l"(a), "l"(b));
}
__device__ __forceinline__ float2 upk2(unsigned long long v) {
    float2 f;
    asm("mov.b64 {%0, %1}, %2;" : "=f"(f.x), "=f"(f.y) : "l"(v));
    return f;
}

// ---------------------------------------------------------------------------
// Scalar NT SGEMM (f32x2, double-buffered) — GEMM2/GEMM3
// ---------------------------------------------------------------------------
template<int BM, int BN, int BK, int TM, int TN, int EPI>
__global__ __launch_bounds__((BM / TM) * (BN / TN), 2)
void gemm_nt(const float* __restrict__ A, int lda,
             const float* __restrict__ Bw, int ldb,
             float* __restrict__ C, int ldc,
             int M, int Nn, int K,
             const float* __restrict__ bias)
{
    constexpr int THREADS = (BM / TM) * (BN / TN);
    constexpr int VPR     = BK / 4;
    constexpr int RS      = THREADS / VPR;
    constexpr int AR      = BM / RS;
    constexpr int BR      = BN / RS;
    constexpr int LDA_S   = BM + 4;
    constexpr int LDB_S   = BN + 4;

    __shared__ float As[2][BK][LDA_S];
    __shared__ float Bs[2][BK][LDB_S];

    const int tid = threadIdx.x;
    const int tx  = tid % (BN / TN);
    const int ty  = tid / (BN / TN);
    const int bm  = blockIdx.y * BM;
    const int bn  = blockIdx.x * BN;
    const int lr  = tid / VPR;
    const int lc  = (tid % VPR) * 4;

    unsigned long long acc[TM][TN / 2] = {};
    float4 ar[AR], br[BR];

    auto ldg = [&](int kt) {
        #pragma unroll
        for (int i = 0; i < AR; ++i)
            ar[i] = *reinterpret_cast<const float4*>(
                &A[(size_t)(bm + i * RS + lr) * lda + kt + lc]);
        #pragma unroll
        for (int i = 0; i < BR; ++i) {
            const int n = bn + i * RS + lr;
            br[i] = (n < Nn)
                  ? *reinterpret_cast<const float4*>(&Bw[(size_t)n * ldb + kt + lc])
                  : make_float4(0.f, 0.f, 0.f, 0.f);
        }
    };
    auto sts = [&](int s) {
        #pragma unroll
        for (int i = 0; i < AR; ++i) {
            As[s][lc + 0][i * RS + lr] = ar[i].x;
            As[s][lc + 1][i * RS + lr] = ar[i].y;
            As[s][lc + 2][i * RS + lr] = ar[i].z;
            As[s][lc + 3][i * RS + lr] = ar[i].w;
        }
        #pragma unroll
        for (int i = 0; i < BR; ++i) {
            Bs[s][lc + 0][i * RS + lr] = br[i].x;
            Bs[s][lc + 1][i * RS + lr] = br[i].y;
            Bs[s][lc + 2][i * RS + lr] = br[i].z;
            Bs[s][lc + 3][i * RS + lr] = br[i].w;
        }
    };

    ldg(0);
    sts(0);
    __syncthreads();

    const int nt = K / BK;
    for (int t = 0; t < nt; ++t) {
        const int cur = t & 1;
        if (t + 1 < nt) ldg((t + 1) * BK);

        #pragma unroll
        for (int k = 0; k < BK; ++k) {
            float4 af[TM / 4], bf[TN / 4];
            #pragma unroll
            for (int i = 0; i < TM / 4; ++i)
                af[i] = *reinterpret_cast<const float4*>(&As[cur][k][ty * TM + 4 * i]);
            #pragma unroll
            for (int j = 0; j < TN / 4; ++j)
                bf[j] = *reinterpret_cast<const float4*>(&Bs[cur][k][tx * TN + 4 * j]);

            unsigned long long bp[TN / 2];
            #pragma unroll
            for (int j = 0; j < TN / 4; ++j) {
                bp[2 * j]     = pk2(bf[j].x, bf[j].y);
                bp[2 * j + 1] = pk2(bf[j].z, bf[j].w);
            }
            const float* afs = reinterpret_cast<const float*>(af);
            #pragma unroll
            for (int i = 0; i < TM; ++i) {
                const unsigned long long a2 = pk2(afs[i], afs[i]);
                #pragma unroll
                for (int j = 0; j < TN / 2; ++j)
                    fma2(acc[i][j], a2, bp[j]);
            }
        }

        if (t + 1 < nt) sts((t + 1) & 1);
        __syncthreads();
    }

    #pragma unroll
    for (int i = 0; i < TM; ++i) {
        const int row = bm + ty * TM + i;
        #pragma unroll
        for (int j = 0; j < TN / 2; ++j) {
            const int col = bn + tx * TN + 2 * j;
            if (col < Nn) {
                float2 p = upk2(acc[i][j]);
                if (EPI == 1) {
                    p.x += bias[col];
                    p.x = (p.x > 20.f) ? p.x : log1pf(__expf(p.x));
                    p.y += bias[col + 1];
                    p.y = (p.y > 20.f) ? p.y : log1pf(__expf(p.y));
                }
                *reinterpret_cast<float2*>(&C[(size_t)row * ldc + col]) = p;
            }
        }
    }
}

// ---------------------------------------------------------------------------
// Depthwise causal conv (K=4) + bias + silu
// ---------------------------------------------------------------------------
__global__ void conv_silu_kernel(const float* __restrict__ xz,
                                 const float* __restrict__ conv_w,
                                 const float* __restrict__ conv_b,
                                 float* __restrict__ xc)
{
    const int d = blockIdx.x * blockDim.x + threadIdx.x;
    const int l = blockIdx.y;
    const int b = blockIdx.z;

    float accv = conv_b[d];
    #pragma unroll
    for (int k = 0; k < Kc; ++k) {
        const int ls = l - (Kc - 1) + k;
        if (ls >= 0)
            accv = fmaf(xz[((size_t)b * Lc + ls) * TWO_DIc + d],
                        conv_w[d * Kc + k], accv);
    }
    const float s = accv / (1.f + __expf(-accv));
    xc[((size_t)b * Lc + l) * DIc + d] = s;
}

// ---------------------------------------------------------------------------
// Selective scan, 4-deep software pipeline (MLP ~20 loads in flight).
// Same arithmetic/order per step as R12 -> bit-identical output.
// ---------------------------------------------------------------------------
__global__ void scan_kernel(const float* __restrict__ dt,
                            const float* __restrict__ dbl,
                            const float* __restrict__ xc,
                            const float* __restrict__ xz,
                            const float* __restrict__ A_log,
                            const float* __restrict__ D_param,
                            __nv_bfloat16* __restrict__ yhi,
                            __nv_bfloat16* __restrict__ ylo)
{
    const int gid  = blockIdx.x * (blockDim.x >> 4) + (threadIdx.x >> 4);
    const int lane = threadIdx.x & 15;
    const int b = gid / DIc;
    const int d = gid % DIc;

    const float An = -__expf(A_log[d * Nc + lane]);
    const float Dd = D_param[d];
    float h = 0.f;

    const float* dt_p = dt  + (size_t)b * Lc * DIc + d;
    const float* xc_p = xc  + (size_t)b * Lc * DIc + d;
    const float* z_p  = xz  + (size_t)b * Lc * TWO_DIc + DIc + d;
    const float* bc_p = dbl + (size_t)b * Lc * RNc + Rc;
    __nv_bfloat16* yh_p = yhi + (size_t)b * Lc * DIc + d;
    __nv_bfloat16* yl_p = ylo + (size_t)b * Lc * DIc + d;

    float bdt[4], bxc[4], bB[4], bC[4], bz[4];
    #pragma unroll
    for (int i = 0; i < 4; ++i) {
        bdt[i] = dt_p[(size_t)i * DIc];
        bxc[i] = xc_p[(size_t)i * DIc];
        bB[i]  = bc_p[(size_t)i * RNc + lane];
        bC[i]  = bc_p[(size_t)i * RNc + Nc + lane];
        bz[i]  = z_p[(size_t)i * TWO_DIc];
    }

    for (int l = 0; l < Lc; l += 4) {
        float ndt[4], nxc[4], nB[4], nC[4], nz[4];
        if (l + 4 < Lc) {
            #pragma unroll
            for (int i = 0; i < 4; ++i) {
                const int ls = l + 4 + i;
                ndt[i] = dt_p[(size_t)ls * DIc];
                nxc[i] = xc_p[(size_t)ls * DIc];
                nB[i]  = bc_p[(size_t)ls * RNc + lane];
                nC[i]  = bc_p[(size_t)ls * RNc + Nc + lane];
                nz[i]  = z_p[(size_t)ls * TWO_DIc];
            }
        } else {
            #pragma unroll
            for (int i = 0; i < 4; ++i) {
                ndt[i] = 0.f; nxc[i] = 0.f; nB[i] = 0.f; nC[i] = 0.f; nz[i] = 0.f;
            }
        }

        #pragma unroll
        for (int i = 0; i < 4; ++i) {
            const float dA = __expf(bdt[i] * An);
            h = fmaf(dA, h, bdt[i] * bB[i] * bxc[i]);
            float v = h * bC[i];
            v += __shfl_xor_sync(0xffffffffu, v, 8);
            v += __shfl_xor_sync(0xffffffffu, v, 4);
            v += __shfl_xor_sync(0xffffffffu, v, 2);
            v += __shfl_xor_sync(0xffffffffu, v, 1);
            if (lane == 0) {
                const float zv = bz[i];
                float yv = (v + bxc[i] * Dd) * (zv / (1.f + __expf(-zv)));
                const __nv_bfloat16 hh = __float2bfloat16(yv);
                yh_p[(size_t)(l + i) * DIc] = hh;
                yl_p[(size_t)(l + i) * DIc] =
                    __float2bfloat16(yv - __bfloat162float(hh));
            }
        }

        #pragma unroll
        for (int i = 0; i < 4; ++i) {
            bdt[i] = ndt[i]; bxc[i] = nxc[i]; bB[i] = nB[i];
            bC[i] = nC[i];   bz[i] = nz[i];
        }
    }
}

// ---------------------------------------------------------------------------
extern "C" void kernel_launch(void* const* d_in, const int* in_sizes, int n_in,
                              void* d_out, int out_size)
{
    const float* x       = (const float*)d_in[0];
    const float* W_in    = (const float*)d_in[1];
    const float* conv_w  = (const float*)d_in[2];
    const float* conv_b  = (const float*)d_in[3];
    const float* W_xproj = (const float*)d_in[4];
    const float* W_dt    = (const float*)d_in[5];
    const float* dt_bias = (const float*)d_in[6];
    const float* A_log   = (const float*)d_in[7];
    const float* D_param = (const float*)d_in[8];
    const float* W_out   = (const float*)d_in[9];
    float* out = (float*)d_out;

    float *xz, *xc, *dbl, *dtb;
    __nv_bfloat16 *xhi, *xlo, *wihi, *wilo, *yhi, *ylo, *wohi, *wolo;
    cudaGetSymbolAddress((void**)&xz,   g_xz);
    cudaGetSymbolAddress((void**)&xc,   g_xc);
    cudaGetSymbolAddress((void**)&dbl,  g_dbl);
    cudaGetSymbolAddress((void**)&dtb,  g_dt);
    cudaGetSymbolAddress((void**)&xhi,  g_xhi);
    cudaGetSymbolAddress((void**)&xlo,  g_xlo);
    cudaGetSymbolAddress((void**)&wihi, g_wihi);
    cudaGetSymbolAddress((void**)&wilo, g_wilo);
    cudaGetSymbolAddress((void**)&yhi,  g_yhi);
    cudaGetSymbolAddress((void**)&ylo,  g_ylo);
    cudaGetSymbolAddress((void**)&wohi, g_wohi);
    cudaGetSymbolAddress((void**)&wolo, g_wolo);

    const int M = Bc * Lc;  // 8192
    const int TENSOR_SMEM = 2 * TSTAGE;

    cudaFuncSetAttribute(gemm_mma,
                         cudaFuncAttributeMaxDynamicSharedMemorySize, TENSOR_SMEM);

    // Split inputs to bf16 hi/lo
    split_kernel<<<(M * Dc / 4 + 255) / 256, 256>>>(x, xhi, xlo, M * Dc);
    split_kernel<<<(TWO_DIc * Dc / 4 + 255) / 256, 256>>>(W_in, wihi, wilo, TWO_DIc * Dc);
    split_kernel<<<(Dc * DIc / 4 + 255) / 256, 256>>>(W_out, wohi, wolo, Dc * DIc);

    // GEMM1 (tensor): xz[M,4096] = x @ W_in^T
    gemm_mma<<<dim3(TWO_DIc / 128, M / 128), 256, TENSOR_SMEM>>>(
        xhi, xlo, wihi, wilo, xz, Dc, TWO_DIc);

    // Depthwise causal conv + silu -> xc
    conv_silu_kernel<<<dim3(DIc / 256, Lc, Bc), 256>>>(xz, conv_w, conv_b, xc);

    // GEMM2 (scalar): dbl[M,96] = xc @ W_xproj^T
    gemm_nt<32, 128, 16, 4, 8, 0><<<dim3(1, M / 32), 128>>>(
        xc, DIc, W_xproj, DIc, dbl, RNc, M, RNc, DIc, nullptr);

    // GEMM3 (scalar): dt[M,2048] = softplus(dbl[:, :64] @ W_dt^T + dt_bias)
    gemm_nt<128, 128, 16, 8, 8, 1><<<dim3(DIc / 128, M / 128), 256>>>(
        dbl, RNc, W_dt, Rc, dtb, DIc, M, DIc, Rc, dt_bias);

    // Selective scan -> y (bf16 hi/lo)
    scan_kernel<<<(Bc * DIc) / 16, 256>>>(dtb, dbl, xc, xz, A_log, D_param, yhi, ylo);

    // GEMM4 (tensor): out[M,1024] = y @ W_out^T
    gemm_mma<<<dim3(Dc / 128, M / 128), 256, TENSOR_SMEM>>>(
        yhi, ylo, wohi, wolo, out, DIc, Dc);
}

// round 14
// speedup vs baseline: 1.2859x; 1.0023x over previous
#include <cuda_runtime.h>
#include <cuda_bf16.h>
#include <math.h>
#include <stdint.h>

// Problem constants
#define Bc      4
#define Lc      2048
#define Dc      1024
#define DIc     2048
#define TWO_DIc 4096
#define Nc      16
#define Kc      4
#define Rc      64
#define RNc     96    // R + 2N

// fp32 scratch
__device__ float g_xz [(size_t)Bc * Lc * TWO_DIc];
__device__ float g_xc [(size_t)Bc * Lc * DIc];
__device__ float g_dbl[(size_t)Bc * Lc * RNc];
__device__ float g_dt [(size_t)Bc * Lc * DIc];
// transposed [b][d][l] operands for the scan
__device__ float g_dtT[(size_t)Bc * DIc * Lc];
__device__ float g_xcT[(size_t)Bc * DIc * Lc];
__device__ float g_zT [(size_t)Bc * DIc * Lc];

// bf16 split scratch (hi/lo)
__device__ __nv_bfloat16 g_xhi [(size_t)Bc * Lc * Dc];
__device__ __nv_bfloat16 g_xlo [(size_t)Bc * Lc * Dc];
__device__ __nv_bfloat16 g_wihi[(size_t)TWO_DIc * Dc];
__device__ __nv_bfloat16 g_wilo[(size_t)TWO_DIc * Dc];
__device__ __nv_bfloat16 g_yhi [(size_t)Bc * Lc * DIc];
__device__ __nv_bfloat16 g_ylo [(size_t)Bc * Lc * DIc];
__device__ __nv_bfloat16 g_wohi[(size_t)Dc * DIc];
__device__ __nv_bfloat16 g_wolo[(size_t)Dc * DIc];

// ---------------------------------------------------------------------------
// Helpers
// ---------------------------------------------------------------------------
__device__ __forceinline__ uint32_t smem_u32(const void* p) {
    uint32_t a;
    asm("{ .reg .u64 t; cvta.to.shared.u64 t, %1; cvt.u32.u64 %0, t; }"
        : "=r"(a) : "l"(p));
    return a;
}
__device__ __forceinline__ void cpa16(uint32_t dst, const void* src) {
    asm volatile("cp.async.cg.shared.global [%0], [%1], 16;"
                 :: "r"(dst), "l"(src) : "memory");
}
__device__ __forceinline__ void mma_bf16(float* c, const uint32_t* a, const uint32_t* b) {
    asm volatile(
        "mma.sync.aligned.m16n8k16.row.col.f32.bf16.bf16.f32 "
        "{%0,%1,%2,%3}, {%4,%5,%6,%7}, {%8,%9}, {%0,%1,%2,%3};"
        : "+f"(c[0]), "+f"(c[1]), "+f"(c[2]), "+f"(c[3])
        : "r"(a[0]), "r"(a[1]), "r"(a[2]), "r"(a[3]), "r"(b[0]), "r"(b[1]));
}
__device__ __forceinline__ void ldm_x4(uint32_t* r, uint32_t addr) {
    asm volatile("ldmatrix.sync.aligned.m8n8.x4.shared.b16 {%0,%1,%2,%3}, [%4];"
                 : "=r"(r[0]), "=r"(r[1]), "=r"(r[2]), "=r"(r[3]) : "r"(addr));
}
__device__ __forceinline__ void ldm_x2(uint32_t* r, uint32_t addr) {
    asm volatile("ldmatrix.sync.aligned.m8n8.x2.shared.b16 {%0,%1}, [%2];"
                 : "=r"(r[0]), "=r"(r[1]) : "r"(addr));
}

// ---------------------------------------------------------------------------
// Split fp32 -> bf16 hi/lo
// ---------------------------------------------------------------------------
__global__ void split_kernel(const float* __restrict__ src,
                             __nv_bfloat16* __restrict__ hi,
                             __nv_bfloat16* __restrict__ lo, int n)
{
    const int i = (blockIdx.x * blockDim.x + threadIdx.x) * 4;
    if (i >= n) return;
    const float4 v = *reinterpret_cast<const float4*>(src + i);
    __nv_bfloat16 h[4], l[4];
    const float f[4] = {v.x, v.y, v.z, v.w};
    #pragma unroll
    for (int j = 0; j < 4; ++j) {
        h[j] = __float2bfloat16(f[j]);
        l[j] = __float2bfloat16(f[j] - __bfloat162float(h[j]));
    }
    *reinterpret_cast<__nv_bfloat162*>(hi + i)     = __nv_bfloat162(h[0], h[1]);
    *reinterpret_cast<__nv_bfloat162*>(hi + i + 2) = __nv_bfloat162(h[2], h[3]);
    *reinterpret_cast<__nv_bfloat162*>(lo + i)     = __nv_bfloat162(l[0], l[1]);
    *reinterpret_cast<__nv_bfloat162*>(lo + i + 2) = __nv_bfloat162(l[2], l[3]);
}

// ---------------------------------------------------------------------------
// Split-bf16 tensor-core GEMM (HMMA) — as R12/R13 (passing)
// ---------------------------------------------------------------------------
#define TSTAGE 40960
#define TROW   80

__global__ __launch_bounds__(256, 2)
void gemm_mma(const __nv_bfloat16* __restrict__ Ahi,
              const __nv_bfloat16* __restrict__ Alo,
              const __nv_bfloat16* __restrict__ Bhi,
              const __nv_bfloat16* __restrict__ Blo,
              float* __restrict__ C, int K, int ldc)
{
    extern __shared__ char smem[];
    const uint32_t sm0 = smem_u32(smem);
    const int tid  = threadIdx.x;
    const int wid  = tid >> 5;
    const int lane = tid & 31;
    const int wm   = wid >> 2;
    const int wn   = wid & 3;
    const int bm   = blockIdx.y * 128;
    const int bn   = blockIdx.x * 128;
    const int g    = lane >> 2;
    const int q    = lane & 3;

    const uint32_t aoffL = (uint32_t)(lane & 15) * TROW + (uint32_t)(lane >> 4) * 16;
    const uint32_t boffL = (uint32_t)(lane & 7) * TROW + (uint32_t)((lane >> 3) & 1) * 16;

    float acc[4][4][4] = {};

    auto stage_load = [&](int kt, int s) {
        const uint32_t sb = sm0 + s * TSTAGE;
        #pragma unroll
        for (int i = 0; i < 2; ++i) {
            const int idx = tid + 256 * i;
            const int row = idx >> 2;
            const int c4  = idx & 3;
            const uint32_t so = (uint32_t)row * TROW + c4 * 16;
            const size_t goA = (size_t)(bm + row) * K + kt + c4 * 8;
            const size_t goB = (size_t)(bn + row) * K + kt + c4 * 8;
            cpa16(sb + so,         Ahi + goA);
            cpa16(sb + 10240 + so, Alo + goA);
            cpa16(sb + 20480 + so, Bhi + goB);
            cpa16(sb + 30720 + so, Blo + goB);
        }
        asm volatile("cp.async.commit_group;" ::: "memory");
    };

    stage_load(0, 0);

    const int nt_iters = K / 32;
    for (int t = 0; t < nt_iters; ++t) {
        asm volatile("cp.async.wait_group 0;" ::: "memory");
        __syncthreads();
        if (t + 1 < nt_iters) stage_load((t + 1) * 32, (t + 1) & 1);

        const uint32_t stg = sm0 + (t & 1) * TSTAGE;
        #pragma unroll
        for (int ks = 0; ks < 2; ++ks) {
            uint32_t a_hi[4][4], a_lo[4][4];
            #pragma unroll
            for (int mt = 0; mt < 4; ++mt) {
                const uint32_t ab = stg + (uint32_t)(wm * 64 + mt * 16) * TROW
                                        + ks * 32 + aoffL;
                ldm_x4(a_hi[mt], ab);
                ldm_x4(a_lo[mt], ab + 10240);
            }
            #pragma unroll
            for (int nt = 0; nt < 4; ++nt) {
                const uint32_t bb = stg + 20480 + (uint32_t)(wn * 32 + nt * 8) * TROW
                                        + ks * 32 + boffL;
                uint32_t bh[2], bl2[2];
                ldm_x2(bh,  bb);
                ldm_x2(bl2, bb + 10240);
                #pragma unroll
                for (int mt = 0; mt < 4; ++mt)
                    mma_bf16(acc[mt][nt], a_hi[mt], bh);
                #pragma unroll
                for (int mt = 0; mt < 4; ++mt)
                    mma_bf16(acc[mt][nt], a_hi[mt], bl2);
                #pragma unroll
                for (int mt = 0; mt < 4; ++mt)
                    mma_bf16(acc[mt][nt], a_lo[mt], bh);
            }
        }
        __syncthreads();
    }

    #pragma unroll
    for (int mt = 0; mt < 4; ++mt) {
        const int r0 = bm + wm * 64 + mt * 16 + g;
        #pragma unroll
        for (int nt = 0; nt < 4; ++nt) {
            const int c0 = bn + wn * 32 + nt * 8 + q * 2;
            *reinterpret_cast<float2*>(&C[(size_t)r0 * ldc + c0]) =
                make_float2(acc[mt][nt][0], acc[mt][nt][1]);
            *reinterpret_cast<float2*>(&C[(size_t)(r0 + 8) * ldc + c0]) =
                make_float2(acc[mt][nt][2], acc[mt][nt][3]);
        }
    }
}

// ---------------------------------------------------------------------------
// Packed f32x2 helpers
// ---------------------------------------------------------------------------
__device__ __forceinline__ unsigned long long pk2(float lo, float hi) {
    unsigned long long r;
    asm("mov.b64 %0, {%1, %2};" : "=l"(r) : "f"(lo), "f"(hi));
    return r;
}
__device__ __forceinline__ void fma2(unsigned long long& d,
                                     unsigned long long a, unsigned long long b) {
    asm("fma.rn.f32x2 %0, %1, %2, %0;" : "+l"(d) : "l"(a), "l"(b));
}
__device__ __forceinline__ float2 upk2(unsigned long long v) {
    float2 f;
    asm("mov.b64 {%0, %1}, %2;" : "=f"(f.x), "=f"(f.y) : "l"(v));
    return f;
}

// ---------------------------------------------------------------------------
// Scalar NT SGEMM (f32x2, double-buffered) — GEMM2/GEMM3
// ---------------------------------------------------------------------------
template<int BM, int BN, int BK, int TM, int TN, int EPI>
__global__ __launch_bounds__((BM / TM) * (BN / TN), 2)
void gemm_nt(const float* __restrict__ A, int lda,
             const float* __restrict__ Bw, int ldb,
             float* __restrict__ C, int ldc,
             int M, int Nn, int K,
             const float* __restrict__ bias)
{
    constexpr int THREADS = (BM / TM) * (BN / TN);
    constexpr int VPR     = BK / 4;
    constexpr int RS      = THREADS / VPR;
    constexpr int AR      = BM / RS;
    constexpr int BR      = BN / RS;
    constexpr int LDA_S   = BM + 4;
    constexpr int LDB_S   = BN + 4;

    __shared__ float As[2][BK][LDA_S];
    __shared__ float Bs[2][BK][LDB_S];

    const int tid = threadIdx.x;
    const int tx  = tid % (BN / TN);
    const int ty  = tid / (BN / TN);
    const int bm  = blockIdx.y * BM;
    const int bn  = blockIdx.x * BN;
    const int lr  = tid / VPR;
    const int lc  = (tid % VPR) * 4;

    unsigned long long acc[TM][TN / 2] = {};
    float4 ar[AR], br[BR];

    auto ldg = [&](int kt) {
        #pragma unroll
        for (int i = 0; i < AR; ++i)
            ar[i] = *reinterpret_cast<const float4*>(
                &A[(size_t)(bm + i * RS + lr) * lda + kt + lc]);
        #pragma unroll
        for (int i = 0; i < BR; ++i) {
            const int n = bn + i * RS + lr;
            br[i] = (n < Nn)
                  ? *reinterpret_cast<const float4*>(&Bw[(size_t)n * ldb + kt + lc])
                  : make_float4(0.f, 0.f, 0.f, 0.f);
        }
    };
    auto sts = [&](int s) {
        #pragma unroll
        for (int i = 0; i < AR; ++i) {
            As[s][lc + 0][i * RS + lr] = ar[i].x;
            As[s][lc + 1][i * RS + lr] = ar[i].y;
            As[s][lc + 2][i * RS + lr] = ar[i].z;
            As[s][lc + 3][i * RS + lr] = ar[i].w;
        }
        #pragma unroll
        for (int i = 0; i < BR; ++i) {
            Bs[s][lc + 0][i * RS + lr] = br[i].x;
            Bs[s][lc + 1][i * RS + lr] = br[i].y;
            Bs[s][lc + 2][i * RS + lr] = br[i].z;
            Bs[s][lc + 3][i * RS + lr] = br[i].w;
        }
    };

    ldg(0);
    sts(0);
    __syncthreads();

    const int nt = K / BK;
    for (int t = 0; t < nt; ++t) {
        const int cur = t & 1;
        if (t + 1 < nt) ldg((t + 1) * BK);

        #pragma unroll
        for (int k = 0; k < BK; ++k) {
            float4 af[TM / 4], bf[TN / 4];
            #pragma unroll
            for (int i = 0; i < TM / 4; ++i)
                af[i] = *reinterpret_cast<const float4*>(&As[cur][k][ty * TM + 4 * i]);
            #pragma unroll
            for (int j = 0; j < TN / 4; ++j)
                bf[j] = *reinterpret_cast<const float4*>(&Bs[cur][k][tx * TN + 4 * j]);

            unsigned long long bp[TN / 2];
            #pragma unroll
            for (int j = 0; j < TN / 4; ++j) {
                bp[2 * j]     = pk2(bf[j].x, bf[j].y);
                bp[2 * j + 1] = pk2(bf[j].z, bf[j].w);
            }
            const float* afs = reinterpret_cast<const float*>(af);
            #pragma unroll
            for (int i = 0; i < TM; ++i) {
                const unsigned long long a2 = pk2(afs[i], afs[i]);
                #pragma unroll
                for (int j = 0; j < TN / 2; ++j)
                    fma2(acc[i][j], a2, bp[j]);
            }
        }

        if (t + 1 < nt) sts((t + 1) & 1);
        __syncthreads();
    }

    #pragma unroll
    for (int i = 0; i < TM; ++i) {
        const int row = bm + ty * TM + i;
        #pragma unroll
        for (int j = 0; j < TN / 2; ++j) {
            const int col = bn + tx * TN + 2 * j;
            if (col < Nn) {
                float2 p = upk2(acc[i][j]);
                if (EPI == 1) {
                    p.x += bias[col];
                    p.x = (p.x > 20.f) ? p.x : log1pf(__expf(p.x));
                    p.y += bias[col + 1];
                    p.y = (p.y > 20.f) ? p.y : log1pf(__expf(p.y));
                }
                *reinterpret_cast<float2*>(&C[(size_t)row * ldc + col]) = p;
            }
        }
    }
}

// ---------------------------------------------------------------------------
// Depthwise causal conv (K=4) + bias + silu
// ---------------------------------------------------------------------------
__global__ void conv_silu_kernel(const float* __restrict__ xz,
                                 const float* __restrict__ conv_w,
                                 const float* __restrict__ conv_b,
                                 float* __restrict__ xc)
{
    const int d = blockIdx.x * blockDim.x + threadIdx.x;
    const int l = blockIdx.y;
    const int b = blockIdx.z;

    float accv = conv_b[d];
    #pragma unroll
    for (int k = 0; k < Kc; ++k) {
        const int ls = l - (Kc - 1) + k;
        if (ls >= 0)
            accv = fmaf(xz[((size_t)b * Lc + ls) * TWO_DIc + d],
                        conv_w[d * Kc + k], accv);
    }
    const float s = accv / (1.f + __expf(-accv));
    xc[((size_t)b * Lc + l) * DIc + d] = s;
}

// ---------------------------------------------------------------------------
// Transpose dt, xc, z([b][l][d]-ish) -> [b][d][l], smem 32x32 tiles
// ---------------------------------------------------------------------------
__global__ void transpose3_kernel(const float* __restrict__ dt,
                                  const float* __restrict__ xc,
                                  const float* __restrict__ xz,
                                  float* __restrict__ dtT,
                                  float* __restrict__ xcT,
                                  float* __restrict__ zT)
{
    __shared__ float tile[32][33];
    const int b  = blockIdx.z;
    const int l0 = blockIdx.x * 32;
    const int d0 = blockIdx.y * 32;
    const int tx = threadIdx.x;   // 0..31
    const int ty = threadIdx.y;   // 0..7

    #pragma unroll
    for (int arr = 0; arr < 3; ++arr) {
        const float* src;
        size_t rstride;
        float* dst;
        if (arr == 0)      { src = dt + (size_t)b * Lc * DIc;            rstride = DIc;     dst = dtT; }
        else if (arr == 1) { src = xc + (size_t)b * Lc * DIc;            rstride = DIc;     dst = xcT; }
        else               { src = xz + (size_t)b * Lc * TWO_DIc + DIc;  rstride = TWO_DIc; dst = zT;  }
        dst += ((size_t)b * DIc + d0) * Lc + l0;

        if (arr) __syncthreads();   // protect smem reuse
        #pragma unroll
        for (int r = 0; r < 32; r += 8)
            tile[ty + r][tx] = src[(size_t)(l0 + ty + r) * rstride + d0 + tx];
        __syncthreads();
        #pragma unroll
        for (int r = 0; r < 32; r += 8)
            dst[(size_t)(ty + r) * Lc + tx] = tile[tx][ty + r];
    }
}

// ---------------------------------------------------------------------------
// Selective scan. dt/xc/z read from [b][d][l] layout as broadcast float4
// (one load per 4 steps per array). B/C per-step as before. Per-step
// arithmetic/order identical to R13 -> bit-identical output.
// ---------------------------------------------------------------------------
__global__ void scan_kernel(const float* __restrict__ dtT,
                            const float* __restrict__ xcT,
                            const float* __restrict__ zT,
                            const float* __restrict__ dbl,
                            const float* __restrict__ A_log,
                            const float* __restrict__ D_param,
                            __nv_bfloat16* __restrict__ yhi,
                            __nv_bfloat16* __restrict__ ylo)
{
    const int gid  = blockIdx.x * (blockDim.x >> 4) + (threadIdx.x >> 4);
    const int lane = threadIdx.x & 15;
    const int b = gid / DIc;
    const int d = gid % DIc;

    const float An = -__expf(A_log[d * Nc + lane]);
    const float Dd = D_param[d];
    float h = 0.f;

    const size_t chan = (size_t)b * DIc + d;
    const float4* dt4 = reinterpret_cast<const float4*>(dtT + chan * Lc);
    const float4* xc4 = reinterpret_cast<const float4*>(xcT + chan * Lc);
    const float4* z4  = reinterpret_cast<const float4*>(zT  + chan * Lc);
    const float* bc_p = dbl + (size_t)b * Lc * RNc + Rc;
    __nv_bfloat16* yh_p = yhi + (size_t)b * Lc * DIc + d;
    __nv_bfloat16* yl_p = ylo + (size_t)b * Lc * DIc + d;

    float4 fdt = dt4[0], fxc = xc4[0], fz = z4[0];
    float bB[4], bC[4];
    #pragma unroll
    for (int i = 0; i < 4; ++i) {
        bB[i] = bc_p[(size_t)i * RNc + lane];
        bC[i] = bc_p[(size_t)i * RNc + Nc + lane];
    }

    for (int l = 0; l < Lc; l += 4) {
        float4 ndt, nxc, nz;
        float nB[4], nC[4];
        if (l + 4 < Lc) {
            const int q4 = (l + 4) >> 2;
            ndt = dt4[q4]; nxc = xc4[q4]; nz = z4[q4];
            #pragma unroll
            for (int i = 0; i < 4; ++i) {
                nB[i] = bc_p[(size_t)(l + 4 + i) * RNc + lane];
                nC[i] = bc_p[(size_t)(l + 4 + i) * RNc + Nc + lane];
            }
        } else {
            ndt = make_float4(0.f, 0.f, 0.f, 0.f);
            nxc = ndt; nz = ndt;
            #pragma unroll
            for (int i = 0; i < 4; ++i) { nB[i] = 0.f; nC[i] = 0.f; }
        }

        const float sdt[4] = {fdt.x, fdt.y, fdt.z, fdt.w};
        const float sxc[4] = {fxc.x, fxc.y, fxc.z, fxc.w};
        const float sz [4] = {fz.x,  fz.y,  fz.z,  fz.w};

        #pragma unroll
        for (int i = 0; i < 4; ++i) {
            const float dA = __expf(sdt[i] * An);
            h = fmaf(dA, h, sdt[i] * bB[i] * sxc[i]);
            float v = h * bC[i];
            v += __shfl_xor_sync(0xffffffffu, v, 8);
            v += __shfl_xor_sync(0xffffffffu, v, 4);
            v += __shfl_xor_sync(0xffffffffu, v, 2);
            v += __shfl_xor_sync(0xffffffffu, v, 1);
            if (lane == 0) {
                const float zv = sz[i];
                float yv = (v + sxc[i] * Dd) * (zv / (1.f + __expf(-zv)));
                const __nv_bfloat16 hh = __float2bfloat16(yv);
                yh_p[(size_t)(l + i) * DIc] = hh;
                yl_p[(size_t)(l + i) * DIc] =
                    __float2bfloat16(yv - __bfloat162float(hh));
            }
        }

        fdt = ndt; fxc = nxc; fz = nz;
        #pragma unroll
        for (int i = 0; i < 4; ++i) { bB[i] = nB[i]; bC[i] = nC[i]; }
    }
}

// ---------------------------------------------------------------------------
extern "C" void kernel_launch(void* const* d_in, const int* in_sizes, int n_in,
                              void* d_out, int out_size)
{
    const float* x       = (const float*)d_in[0];
    const float* W_in    = (const float*)d_in[1];
    const float* conv_w  = (const float*)d_in[2];
    const float* conv_b  = (const float*)d_in[3];
    const float* W_xproj = (const float*)d_in[4];
    const float* W_dt    = (const float*)d_in[5];
    const float* dt_bias = (const float*)d_in[6];
    const float* A_log   = (const float*)d_in[7];
    const float* D_param = (const float*)d_in[8];
    const float* W_out   = (const float*)d_in[9];
    float* out = (float*)d_out;

    float *xz, *xc, *dbl, *dtb, *dtT, *xcT, *zT;
    __nv_bfloat16 *xhi, *xlo, *wihi, *wilo, *yhi, *ylo, *wohi, *wolo;
    cudaGetSymbolAddress((void**)&xz,   g_xz);
    cudaGetSymbolAddress((void**)&xc,   g_xc);
    cudaGetSymbolAddress((void**)&dbl,  g_dbl);
    cudaGetSymbolAddress((void**)&dtb,  g_dt);
    cudaGetSymbolAddress((void**)&dtT,  g_dtT);
    cudaGetSymbolAddress((void**)&xcT,  g_xcT);
    cudaGetSymbolAddress((void**)&zT,   g_zT);
    cudaGetSymbolAddress((void**)&xhi,  g_xhi);
    cudaGetSymbolAddress((void**)&xlo,  g_xlo);
    cudaGetSymbolAddress((void**)&wihi, g_wihi);
    cudaGetSymbolAddress((void**)&wilo, g_wilo);
    cudaGetSymbolAddress((void**)&yhi,  g_yhi);
    cudaGetSymbolAddress((void**)&ylo,  g_ylo);
    cudaGetSymbolAddress((void**)&wohi, g_wohi);
    cudaGetSymbolAddress((void**)&wolo, g_wolo);

    const int M = Bc * Lc;  // 8192
    const int TENSOR_SMEM = 2 * TSTAGE;

    cudaFuncSetAttribute(gemm_mma,
                         cudaFuncAttributeMaxDynamicSharedMemorySize, TENSOR_SMEM);

    // Split inputs to bf16 hi/lo
    split_kernel<<<(M * Dc / 4 + 255) / 256, 256>>>(x, xhi, xlo, M * Dc);
    split_kernel<<<(TWO_DIc * Dc / 4 + 255) / 256, 256>>>(W_in, wihi, wilo, TWO_DIc * Dc);
    split_kernel<<<(Dc * DIc / 4 + 255) / 256, 256>>>(W_out, wohi, wolo, Dc * DIc);

    // GEMM1 (tensor): xz[M,4096] = x @ W_in^T
    gemm_mma<<<dim3(TWO_DIc / 128, M / 128), 256, TENSOR_SMEM>>>(
        xhi, xlo, wihi, wilo, xz, Dc, TWO_DIc);

    // Depthwise causal conv + silu -> xc
    conv_silu_kernel<<<dim3(DIc / 256, Lc, Bc), 256>>>(xz, conv_w, conv_b, xc);

    // GEMM2 (scalar): dbl[M,96] = xc @ W_xproj^T
    gemm_nt<32, 128, 16, 4, 8, 0><<<dim3(1, M / 32), 128>>>(
        xc, DIc, W_xproj, DIc, dbl, RNc, M, RNc, DIc, nullptr);

    // GEMM3 (scalar): dt[M,2048] = softplus(dbl[:, :64] @ W_dt^T + dt_bias)
    gemm_nt<128, 128, 16, 8, 8, 1><<<dim3(DIc / 128, M / 128), 256>>>(
        dbl, RNc, W_dt, Rc, dtb, DIc, M, DIc, Rc, dt_bias);

    // Transpose dt, xc, z -> [b][d][l]
    transpose3_kernel<<<dim3(Lc / 32, DIc / 32, Bc), dim3(32, 8)>>>(
        dtb, xc, xz, dtT, xcT, zT);

    // Selective scan -> y (bf16 hi/lo)
    scan_kernel<<<(Bc * DIc) / 16, 256>>>(dtT, xcT, zT, dbl, A_log, D_param,
                                          yhi, ylo);

    // GEMM4 (tensor): out[M,1024] = y @ W_out^T
    gemm_mma<<<dim3(Dc / 128, M / 128), 256, TENSOR_SMEM>>>(
        yhi, ylo, wohi, wolo, out, DIc, Dc);
}

// round 15
// speedup vs baseline: 1.5469x; 1.2030x over previous
#include <cuda_runtime.h>
#include <cuda_bf16.h>
#include <math.h>
#include <stdint.h>

// Problem constants
#define Bc      4
#define Lc      2048
#define Dc      1024
#define DIc     2048
#define TWO_DIc 4096
#define Nc      16
#define Kc      4
#define Rc      64
#define RNc     96    // R + 2N

// fp32 scratch
__device__ float g_xz [(size_t)Bc * Lc * TWO_DIc];
__device__ float g_xc [(size_t)Bc * Lc * DIc];
__device__ float g_dbl[(size_t)Bc * Lc * RNc];
__device__ float g_dt [(size_t)Bc * Lc * DIc];
// transposed [b][d][l] operands for the scan
__device__ float g_dtT[(size_t)Bc * DIc * Lc];
__device__ float g_xcT[(size_t)Bc * DIc * Lc];
__device__ float g_zT [(size_t)Bc * DIc * Lc];

// bf16 split scratch (hi/lo)
__device__ __nv_bfloat16 g_xhi [(size_t)Bc * Lc * Dc];
__device__ __nv_bfloat16 g_xlo [(size_t)Bc * Lc * Dc];
__device__ __nv_bfloat16 g_wihi[(size_t)TWO_DIc * Dc];
__device__ __nv_bfloat16 g_wilo[(size_t)TWO_DIc * Dc];
__device__ __nv_bfloat16 g_yhi [(size_t)Bc * Lc * DIc];
__device__ __nv_bfloat16 g_ylo [(size_t)Bc * Lc * DIc];
__device__ __nv_bfloat16 g_wohi[(size_t)Dc * DIc];
__device__ __nv_bfloat16 g_wolo[(size_t)Dc * DIc];

// ---------------------------------------------------------------------------
// Helpers
// ---------------------------------------------------------------------------
__device__ __forceinline__ uint32_t smem_u32(const void* p) {
    uint32_t a;
    asm("{ .reg .u64 t; cvta.to.shared.u64 t, %1; cvt.u32.u64 %0, t; }"
        : "=r"(a) : "l"(p));
    return a;
}
__device__ __forceinline__ void cpa16(uint32_t dst, const void* src) {
    asm volatile("cp.async.cg.shared.global [%0], [%1], 16;"
                 :: "r"(dst), "l"(src) : "memory");
}
__device__ __forceinline__ void mma_bf16(float* c, const uint32_t* a, const uint32_t* b) {
    asm volatile(
        "mma.sync.aligned.m16n8k16.row.col.f32.bf16.bf16.f32 "
        "{%0,%1,%2,%3}, {%4,%5,%6,%7}, {%8,%9}, {%0,%1,%2,%3};"
        : "+f"(c[0]), "+f"(c[1]), "+f"(c[2]), "+f"(c[3])
        : "r"(a[0]), "r"(a[1]), "r"(a[2]), "r"(a[3]), "r"(b[0]), "r"(b[1]));
}
__device__ __forceinline__ void ldm_x4(uint32_t* r, uint32_t addr) {
    asm volatile("ldmatrix.sync.aligned.m8n8.x4.shared.b16 {%0,%1,%2,%3}, [%4];"
                 : "=r"(r[0]), "=r"(r[1]), "=r"(r[2]), "=r"(r[3]) : "r"(addr));
}
__device__ __forceinline__ void ldm_x2(uint32_t* r, uint32_t addr) {
    asm volatile("ldmatrix.sync.aligned.m8n8.x2.shared.b16 {%0,%1}, [%2];"
                 : "=r"(r[0]), "=r"(r[1]) : "r"(addr));
}

// ---------------------------------------------------------------------------
// Split fp32 -> bf16 hi/lo
// ---------------------------------------------------------------------------
__global__ void split_kernel(const float* __restrict__ src,
                             __nv_bfloat16* __restrict__ hi,
                             __nv_bfloat16* __restrict__ lo, int n)
{
    const int i = (blockIdx.x * blockDim.x + threadIdx.x) * 4;
    if (i >= n) return;
    const float4 v = *reinterpret_cast<const float4*>(src + i);
    __nv_bfloat16 h[4], l[4];
    const float f[4] = {v.x, v.y, v.z, v.w};
    #pragma unroll
    for (int j = 0; j < 4; ++j) {
        h[j] = __float2bfloat16(f[j]);
        l[j] = __float2bfloat16(f[j] - __bfloat162float(h[j]));
    }
    *reinterpret_cast<__nv_bfloat162*>(hi + i)     = __nv_bfloat162(h[0], h[1]);
    *reinterpret_cast<__nv_bfloat162*>(hi + i + 2) = __nv_bfloat162(h[2], h[3]);
    *reinterpret_cast<__nv_bfloat162*>(lo + i)     = __nv_bfloat162(l[0], l[1]);
    *reinterpret_cast<__nv_bfloat162*>(lo + i + 2) = __nv_bfloat162(l[2], l[3]);
}

// ---------------------------------------------------------------------------
// Split-bf16 tensor-core GEMM (HMMA) — as R12-R14 (passing)
// ---------------------------------------------------------------------------
#define TSTAGE 40960
#define TROW   80

__global__ __launch_bounds__(256, 2)
void gemm_mma(const __nv_bfloat16* __restrict__ Ahi,
              const __nv_bfloat16* __restrict__ Alo,
              const __nv_bfloat16* __restrict__ Bhi,
              const __nv_bfloat16* __restrict__ Blo,
              float* __restrict__ C, int K, int ldc)
{
    extern __shared__ char smem[];
    const uint32_t sm0 = smem_u32(smem);
    const int tid  = threadIdx.x;
    const int wid  = tid >> 5;
    const int lane = tid & 31;
    const int wm   = wid >> 2;
    const int wn   = wid & 3;
    const int bm   = blockIdx.y * 128;
    const int bn   = blockIdx.x * 128;
    const int g    = lane >> 2;
    const int q    = lane & 3;

    const uint32_t aoffL = (uint32_t)(lane & 15) * TROW + (uint32_t)(lane >> 4) * 16;
    const uint32_t boffL = (uint32_t)(lane & 7) * TROW + (uint32_t)((lane >> 3) & 1) * 16;

    float acc[4][4][4] = {};

    auto stage_load = [&](int kt, int s) {
        const uint32_t sb = sm0 + s * TSTAGE;
        #pragma unroll
        for (int i = 0; i < 2; ++i) {
            const int idx = tid + 256 * i;
            const int row = idx >> 2;
            const int c4  = idx & 3;
            const uint32_t so = (uint32_t)row * TROW + c4 * 16;
            const size_t goA = (size_t)(bm + row) * K + kt + c4 * 8;
            const size_t goB = (size_t)(bn + row) * K + kt + c4 * 8;
            cpa16(sb + so,         Ahi + goA);
            cpa16(sb + 10240 + so, Alo + goA);
            cpa16(sb + 20480 + so, Bhi + goB);
            cpa16(sb + 30720 + so, Blo + goB);
        }
        asm volatile("cp.async.commit_group;" ::: "memory");
    };

    stage_load(0, 0);

    const int nt_iters = K / 32;
    for (int t = 0; t < nt_iters; ++t) {
        asm volatile("cp.async.wait_group 0;" ::: "memory");
        __syncthreads();
        if (t + 1 < nt_iters) stage_load((t + 1) * 32, (t + 1) & 1);

        const uint32_t stg = sm0 + (t & 1) * TSTAGE;
        #pragma unroll
        for (int ks = 0; ks < 2; ++ks) {
            uint32_t a_hi[4][4], a_lo[4][4];
            #pragma unroll
            for (int mt = 0; mt < 4; ++mt) {
                const uint32_t ab = stg + (uint32_t)(wm * 64 + mt * 16) * TROW
                                        + ks * 32 + aoffL;
                ldm_x4(a_hi[mt], ab);
                ldm_x4(a_lo[mt], ab + 10240);
            }
            #pragma unroll
            for (int nt = 0; nt < 4; ++nt) {
                const uint32_t bb = stg + 20480 + (uint32_t)(wn * 32 + nt * 8) * TROW
                                        + ks * 32 + boffL;
                uint32_t bh[2], bl2[2];
                ldm_x2(bh,  bb);
                ldm_x2(bl2, bb + 10240);
                #pragma unroll
                for (int mt = 0; mt < 4; ++mt)
                    mma_bf16(acc[mt][nt], a_hi[mt], bh);
                #pragma unroll
                for (int mt = 0; mt < 4; ++mt)
                    mma_bf16(acc[mt][nt], a_hi[mt], bl2);
                #pragma unroll
                for (int mt = 0; mt < 4; ++mt)
                    mma_bf16(acc[mt][nt], a_lo[mt], bh);
            }
        }
        __syncthreads();
    }

    #pragma unroll
    for (int mt = 0; mt < 4; ++mt) {
        const int r0 = bm + wm * 64 + mt * 16 + g;
        #pragma unroll
        for (int nt = 0; nt < 4; ++nt) {
            const int c0 = bn + wn * 32 + nt * 8 + q * 2;
            *reinterpret_cast<float2*>(&C[(size_t)r0 * ldc + c0]) =
                make_float2(acc[mt][nt][0], acc[mt][nt][1]);
            *reinterpret_cast<float2*>(&C[(size_t)(r0 + 8) * ldc + c0]) =
                make_float2(acc[mt][nt][2], acc[mt][nt][3]);
        }
    }
}

// ---------------------------------------------------------------------------
// Packed f32x2 helpers
// ---------------------------------------------------------------------------
__device__ __forceinline__ unsigned long long pk2(float lo, float hi) {
    unsigned long long r;
    asm("mov.b64 %0, {%1, %2};" : "=l"(r) : "f"(lo), "f"(hi));
    return r;
}
__device__ __forceinline__ void fma2(unsigned long long& d,
                                     unsigned long long a, unsigned long long b) {
    asm("fma.rn.f32x2 %0, %1, %2, %0;" : "+l"(d) : "l"(a), "l"(b));
}
__device__ __forceinline__ float2 upk2(unsigned long long v) {
    float2 f;
    asm("mov.b64 {%0, %1}, %2;" : "=f"(f.x), "=f"(f.y) : "l"(v));
    return f;
}

// ---------------------------------------------------------------------------
// Scalar NT SGEMM (f32x2, double-buffered) — GEMM2/GEMM3
// ---------------------------------------------------------------------------
template<int BM, int BN, int BK, int TM, int TN, int EPI>
__global__ __launch_bounds__((BM / TM) * (BN / TN), 2)
void gemm_nt(const float* __restrict__ A, int lda,
             const float* __restrict__ Bw, int ldb,
             float* __restrict__ C, int ldc,
             int M, int Nn, int K,
             const float* __restrict__ bias)
{
    constexpr int THREADS = (BM / TM) * (BN / TN);
    constexpr int VPR     = BK / 4;
    constexpr int RS      = THREADS / VPR;
    constexpr int AR      = BM / RS;
    constexpr int BR      = BN / RS;
    constexpr int LDA_S   = BM + 4;
    constexpr int LDB_S   = BN + 4;

    __shared__ float As[2][BK][LDA_S];
    __shared__ float Bs[2][BK][LDB_S];

    const int tid = threadIdx.x;
    const int tx  = tid % (BN / TN);
    const int ty  = tid / (BN / TN);
    const int bm  = blockIdx.y * BM;
    const int bn  = blockIdx.x * BN;
    const int lr  = tid / VPR;
    const int lc  = (tid % VPR) * 4;

    unsigned long long acc[TM][TN / 2] = {};
    float4 ar[AR], br[BR];

    auto ldg = [&](int kt) {
        #pragma unroll
        for (int i = 0; i < AR; ++i)
            ar[i] = *reinterpret_cast<const float4*>(
                &A[(size_t)(bm + i * RS + lr) * lda + kt + lc]);
        #pragma unroll
        for (int i = 0; i < BR; ++i) {
            const int n = bn + i * RS + lr;
            br[i] = (n < Nn)
                  ? *reinterpret_cast<const float4*>(&Bw[(size_t)n * ldb + kt + lc])
                  : make_float4(0.f, 0.f, 0.f, 0.f);
        }
    };
    auto sts = [&](int s) {
        #pragma unroll
        for (int i = 0; i < AR; ++i) {
            As[s][lc + 0][i * RS + lr] = ar[i].x;
            As[s][lc + 1][i * RS + lr] = ar[i].y;
            As[s][lc + 2][i * RS + lr] = ar[i].z;
            As[s][lc + 3][i * RS + lr] = ar[i].w;
        }
        #pragma unroll
        for (int i = 0; i < BR; ++i) {
            Bs[s][lc + 0][i * RS + lr] = br[i].x;
            Bs[s][lc + 1][i * RS + lr] = br[i].y;
            Bs[s][lc + 2][i * RS + lr] = br[i].z;
            Bs[s][lc + 3][i * RS + lr] = br[i].w;
        }
    };

    ldg(0);
    sts(0);
    __syncthreads();

    const int nt = K / BK;
    for (int t = 0; t < nt; ++t) {
        const int cur = t & 1;
        if (t + 1 < nt) ldg((t + 1) * BK);

        #pragma unroll
        for (int k = 0; k < BK; ++k) {
            float4 af[TM / 4], bf[TN / 4];
            #pragma unroll
            for (int i = 0; i < TM / 4; ++i)
                af[i] = *reinterpret_cast<const float4*>(&As[cur][k][ty * TM + 4 * i]);
            #pragma unroll
            for (int j = 0; j < TN / 4; ++j)
                bf[j] = *reinterpret_cast<const float4*>(&Bs[cur][k][tx * TN + 4 * j]);

            unsigned long long bp[TN / 2];
            #pragma unroll
            for (int j = 0; j < TN / 4; ++j) {
                bp[2 * j]     = pk2(bf[j].x, bf[j].y);
                bp[2 * j + 1] = pk2(bf[j].z, bf[j].w);
            }
            const float* afs = reinterpret_cast<const float*>(af);
            #pragma unroll
            for (int i = 0; i < TM; ++i) {
                const unsigned long long a2 = pk2(afs[i], afs[i]);
                #pragma unroll
                for (int j = 0; j < TN / 2; ++j)
                    fma2(acc[i][j], a2, bp[j]);
            }
        }

        if (t + 1 < nt) sts((t + 1) & 1);
        __syncthreads();
    }

    #pragma unroll
    for (int i = 0; i < TM; ++i) {
        const int row = bm + ty * TM + i;
        #pragma unroll
        for (int j = 0; j < TN / 2; ++j) {
            const int col = bn + tx * TN + 2 * j;
            if (col < Nn) {
                float2 p = upk2(acc[i][j]);
                if (EPI == 1) {
                    p.x += bias[col];
                    p.x = (p.x > 20.f) ? p.x : log1pf(__expf(p.x));
                    p.y += bias[col + 1];
                    p.y = (p.y > 20.f) ? p.y : log1pf(__expf(p.y));
                }
                *reinterpret_cast<float2*>(&C[(size_t)row * ldc + col]) = p;
            }
        }
    }
}

// ---------------------------------------------------------------------------
// Depthwise causal conv (K=4) + bias + silu
// ---------------------------------------------------------------------------
__global__ void conv_silu_kernel(const float* __restrict__ xz,
                                 const float* __restrict__ conv_w,
                                 const float* __restrict__ conv_b,
                                 float* __restrict__ xc)
{
    const int d = blockIdx.x * blockDim.x + threadIdx.x;
    const int l = blockIdx.y;
    const int b = blockIdx.z;

    float accv = conv_b[d];
    #pragma unroll
    for (int k = 0; k < Kc; ++k) {
        const int ls = l - (Kc - 1) + k;
        if (ls >= 0)
            accv = fmaf(xz[((size_t)b * Lc + ls) * TWO_DIc + d],
                        conv_w[d * Kc + k], accv);
    }
    const float s = accv / (1.f + __expf(-accv));
    xc[((size_t)b * Lc + l) * DIc + d] = s;
}

// ---------------------------------------------------------------------------
// Transpose dt, xc, z([b][l][d]-ish) -> [b][d][l], smem 32x32 tiles
// ---------------------------------------------------------------------------
__global__ void transpose3_kernel(const float* __restrict__ dt,
                                  const float* __restrict__ xc,
                                  const float* __restrict__ xz,
                                  float* __restrict__ dtT,
                                  float* __restrict__ xcT,
                                  float* __restrict__ zT)
{
    __shared__ float tile[32][33];
    const int b  = blockIdx.z;
    const int l0 = blockIdx.x * 32;
    const int d0 = blockIdx.y * 32;
    const int tx = threadIdx.x;   // 0..31
    const int ty = threadIdx.y;   // 0..7

    #pragma unroll
    for (int arr = 0; arr < 3; ++arr) {
        const float* src;
        size_t rstride;
        float* dst;
        if (arr == 0)      { src = dt + (size_t)b * Lc * DIc;            rstride = DIc;     dst = dtT; }
        else if (arr == 1) { src = xc + (size_t)b * Lc * DIc;            rstride = DIc;     dst = xcT; }
        else               { src = xz + (size_t)b * Lc * TWO_DIc + DIc;  rstride = TWO_DIc; dst = zT;  }
        dst += ((size_t)b * DIc + d0) * Lc + l0;

        if (arr) __syncthreads();   // protect smem reuse
        #pragma unroll
        for (int r = 0; r < 32; r += 8)
            tile[ty + r][tx] = src[(size_t)(l0 + ty + r) * rstride + d0 + tx];
        __syncthreads();
        #pragma unroll
        for (int r = 0; r < 32; r += 8)
            dst[(size_t)(ty + r) * Lc + tx] = tile[tx][ty + r];
    }
}

// ---------------------------------------------------------------------------
// Selective scan, 8 lanes per channel, 2 states per lane, 4 channels/warp.
// dt/xc/z from [b][d][l] (float4 per 4 steps, broadcast within 8-lane group);
// B/C as float2 per lane (states 2j, 2j+1). 3-round xor reduction over the
// 8-lane subgroup. Output written by subgroup lane 0 (4 channels share one
// predicated STG instruction).
// ---------------------------------------------------------------------------
__global__ void scan_kernel(const float* __restrict__ dtT,
                            const float* __restrict__ xcT,
                            const float* __restrict__ zT,
                            const float* __restrict__ dbl,
                            const float* __restrict__ A_log,
                            const float* __restrict__ D_param,
                            __nv_bfloat16* __restrict__ yhi,
                            __nv_bfloat16* __restrict__ ylo)
{
    const int lane  = threadIdx.x & 31;
    const int gwarp = blockIdx.x * (blockDim.x >> 5) + (threadIdx.x >> 5);
    const int chan  = gwarp * 4 + (lane >> 3);    // 0 .. Bc*DIc-1
    const int j     = lane & 7;                   // state pair index
    const int b = chan / DIc;
    const int d = chan % DIc;

    const float An0 = -__expf(A_log[d * Nc + 2 * j]);
    const float An1 = -__expf(A_log[d * Nc + 2 * j + 1]);
    const float Dd  = D_param[d];
    float h0 = 0.f, h1 = 0.f;

    const size_t ch = (size_t)b * DIc + d;
    const float4* dt4 = reinterpret_cast<const float4*>(dtT + ch * Lc);
    const float4* xc4 = reinterpret_cast<const float4*>(xcT + ch * Lc);
    const float4* z4  = reinterpret_cast<const float4*>(zT  + ch * Lc);
    const char* bc_base = reinterpret_cast<const char*>(
        dbl + (size_t)b * Lc * RNc + Rc + 2 * j);
    __nv_bfloat16* yh_p = yhi + (size_t)b * Lc * DIc + d;
    __nv_bfloat16* yl_p = ylo + (size_t)b * Lc * DIc + d;

    float4 fdt = dt4[0], fxc = xc4[0], fz = z4[0];
    float2 fB[4], fC[4];
    #pragma unroll
    for (int i = 0; i < 4; ++i) {
        fB[i] = *reinterpret_cast<const float2*>(bc_base + (size_t)i * RNc * 4);
        fC[i] = *reinterpret_cast<const float2*>(bc_base + (size_t)i * RNc * 4 + Nc * 4);
    }

    for (int l = 0; l < Lc; l += 4) {
        float4 ndt, nxc, nz;
        float2 nB[4], nC[4];
        if (l + 4 < Lc) {
            const int q4 = (l + 4) >> 2;
            ndt = dt4[q4]; nxc = xc4[q4]; nz = z4[q4];
            #pragma unroll
            for (int i = 0; i < 4; ++i) {
                nB[i] = *reinterpret_cast<const float2*>(
                    bc_base + (size_t)(l + 4 + i) * RNc * 4);
                nC[i] = *reinterpret_cast<const float2*>(
                    bc_base + (size_t)(l + 4 + i) * RNc * 4 + Nc * 4);
            }
        } else {
            ndt = make_float4(0.f, 0.f, 0.f, 0.f);
            nxc = ndt; nz = ndt;
            #pragma unroll
            for (int i = 0; i < 4; ++i) {
                nB[i] = make_float2(0.f, 0.f); nC[i] = make_float2(0.f, 0.f);
            }
        }

        const float sdt[4] = {fdt.x, fdt.y, fdt.z, fdt.w};
        const float sxc[4] = {fxc.x, fxc.y, fxc.z, fxc.w};
        const float sz [4] = {fz.x,  fz.y,  fz.z,  fz.w};

        #pragma unroll
        for (int i = 0; i < 4; ++i) {
            const float dA0 = __expf(sdt[i] * An0);
            const float dA1 = __expf(sdt[i] * An1);
            const float dBx = sdt[i] * sxc[i];
            h0 = fmaf(dA0, h0, dBx * fB[i].x);
            h1 = fmaf(dA1, h1, dBx * fB[i].y);
            float v = fmaf(h0, fC[i].x, h1 * fC[i].y);
            v += __shfl_xor_sync(0xffffffffu, v, 4);
            v += __shfl_xor_sync(0xffffffffu, v, 2);
            v += __shfl_xor_sync(0xffffffffu, v, 1);
            if (j == 0) {
                const float zv = sz[i];
                float yv = (v + sxc[i] * Dd) * (zv / (1.f + __expf(-zv)));
                const __nv_bfloat16 hh = __float2bfloat16(yv);
                yh_p[(size_t)(l + i) * DIc] = hh;
                yl_p[(size_t)(l + i) * DIc] =
                    __float2bfloat16(yv - __bfloat162float(hh));
            }
        }

        fdt = ndt; fxc = nxc; fz = nz;
        #pragma unroll
        for (int i = 0; i < 4; ++i) { fB[i] = nB[i]; fC[i] = nC[i]; }
    }
}

// ---------------------------------------------------------------------------
extern "C" void kernel_launch(void* const* d_in, const int* in_sizes, int n_in,
                              void* d_out, int out_size)
{
    const float* x       = (const float*)d_in[0];
    const float* W_in    = (const float*)d_in[1];
    const float* conv_w  = (const float*)d_in[2];
    const float* conv_b  = (const float*)d_in[3];
    const float* W_xproj = (const float*)d_in[4];
    const float* W_dt    = (const float*)d_in[5];
    const float* dt_bias = (const float*)d_in[6];
    const float* A_log   = (const float*)d_in[7];
    const float* D_param = (const float*)d_in[8];
    const float* W_out   = (const float*)d_in[9];
    float* out = (float*)d_out;

    float *xz, *xc, *dbl, *dtb, *dtT, *xcT, *zT;
    __nv_bfloat16 *xhi, *xlo, *wihi, *wilo, *yhi, *ylo, *wohi, *wolo;
    cudaGetSymbolAddress((void**)&xz,   g_xz);
    cudaGetSymbolAddress((void**)&xc,   g_xc);
    cudaGetSymbolAddress((void**)&dbl,  g_dbl);
    cudaGetSymbolAddress((void**)&dtb,  g_dt);
    cudaGetSymbolAddress((void**)&dtT,  g_dtT);
    cudaGetSymbolAddress((void**)&xcT,  g_xcT);
    cudaGetSymbolAddress((void**)&zT,   g_zT);
    cudaGetSymbolAddress((void**)&xhi,  g_xhi);
    cudaGetSymbolAddress((void**)&xlo,  g_xlo);
    cudaGetSymbolAddress((void**)&wihi, g_wihi);
    cudaGetSymbolAddress((void**)&wilo, g_wilo);
    cudaGetSymbolAddress((void**)&yhi,  g_yhi);
    cudaGetSymbolAddress((void**)&ylo,  g_ylo);
    cudaGetSymbolAddress((void**)&wohi, g_wohi);
    cudaGetSymbolAddress((void**)&wolo, g_wolo);

    const int M = Bc * Lc;  // 8192
    const int TENSOR_SMEM = 2 * TSTAGE;

    cudaFuncSetAttribute(gemm_mma,
                         cudaFuncAttributeMaxDynamicSharedMemorySize, TENSOR_SMEM);

    // Split inputs to bf16 hi/lo
    split_kernel<<<(M * Dc / 4 + 255) / 256, 256>>>(x, xhi, xlo, M * Dc);
    split_kernel<<<(TWO_DIc * Dc / 4 + 255) / 256, 256>>>(W_in, wihi, wilo, TWO_DIc * Dc);
    split_kernel<<<(Dc * DIc / 4 + 255) / 256, 256>>>(W_out, wohi, wolo, Dc * DIc);

    // GEMM1 (tensor): xz[M,4096] = x @ W_in^T
    gemm_mma<<<dim3(TWO_DIc / 128, M / 128), 256, TENSOR_SMEM>>>(
        xhi, xlo, wihi, wilo, xz, Dc, TWO_DIc);

    // Depthwise causal conv + silu -> xc
    conv_silu_kernel<<<dim3(DIc / 256, Lc, Bc), 256>>>(xz, conv_w, conv_b, xc);

    // GEMM2 (scalar): dbl[M,96] = xc @ W_xproj^T
    gemm_nt<32, 128, 16, 4, 8, 0><<<dim3(1, M / 32), 128>>>(
        xc, DIc, W_xproj, DIc, dbl, RNc, M, RNc, DIc, nullptr);

    // GEMM3 (scalar): dt[M,2048] = softplus(dbl[:, :64] @ W_dt^T + dt_bias)
    gemm_nt<128, 128, 16, 8, 8, 1><<<dim3(DIc / 128, M / 128), 256>>>(
        dbl, RNc, W_dt, Rc, dtb, DIc, M, DIc, Rc, dt_bias);

    // Transpose dt, xc, z -> [b][d][l]
    transpose3_kernel<<<dim3(Lc / 32, DIc / 32, Bc), dim3(32, 8)>>>(
        dtb, xc, xz, dtT, xcT, zT);

    // Selective scan -> y (bf16 hi/lo). 4 channels per warp, 8 warps/block:
    // 32 channels per block -> 256 blocks.
    scan_kernel<<<(Bc * DIc) / 32, 256>>>(dtT, xcT, zT, dbl, A_log, D_param,
                                          yhi, ylo);

    // GEMM4 (tensor): out[M,1024] = y @ W_out^T
    gemm_mma<<<dim3(Dc / 128, M / 128), 256, TENSOR_SMEM>>>(
        yhi, ylo, wohi, wolo, out, DIc, Dc);
}